// round 6
// baseline (speedup 1.0000x reference)
#include <cuda_runtime.h>
#include <cuda_bf16.h>
#include <stdint.h>

// ============================ problem constants ============================
#define F_DIM   39
#define NT      512
#define MT      128              // rows (b,d) per CTA
#define NCH0    24               // layer0 k64 chunks (K padded 1521->1536)
#define NCH12   78               // layer1/2 chunks (4992 exact)
#define NCHT    (NCH0 + 2*NCH12) // 180
#define K0_REAL 1521
#define K12     4992
#define CHUNK_ELEMS 16384        // 64 k x 256 n

// weights pre-shuffled into per-lane mma fragment order, bf16 hi/lo
__device__ __align__(256) __nv_bfloat16 g_Bh[(size_t)NCHT * CHUNK_ELEMS];
__device__ __align__(256) __nv_bfloat16 g_Bl[(size_t)NCHT * CHUNK_ELEMS];

// ============================ smem layout (bytes) ==========================
#define B_BUF  65536                     // per buffer: hi 32KB + lo 32KB
#define SM_B   0
#define SM_X   (2*B_BUF)                 // 131072 : x fp32 [128][XS]
#define XS     41
#define SM_H   (SM_X + 128*XS*4)         // 152064 : h fp32 [128][HS]
#define HS     132
#define SM_RS  (SM_H + 128*HS*4)         // 219648 : rowsum[128]
#define SM_TOT (SM_RS + 512)             // 220160

// ============================ helpers ======================================
__device__ __forceinline__ uint32_t s2u(const void* p) {
    uint32_t a;
    asm("{ .reg .u64 t; cvta.to.shared.u64 t, %1; cvt.u32.u64 %0, t; }" : "=r"(a) : "l"(p));
    return a;
}
__device__ __forceinline__ void cp16(uint32_t s, const void* g) {
    asm volatile("cp.async.cg.shared.global [%0], [%1], 16;" :: "r"(s), "l"(g));
}
#define CP_COMMIT() asm volatile("cp.async.commit_group;")
#define CP_WAIT1()  asm volatile("cp.async.wait_group 1;" ::: "memory")

__device__ __forceinline__ void mma_bf16(float* c, const uint32_t* a, uint32_t b0, uint32_t b1) {
    asm volatile("mma.sync.aligned.m16n8k16.row.col.f32.bf16.bf16.f32 "
        "{%0,%1,%2,%3}, {%4,%5,%6,%7}, {%8,%9}, {%0,%1,%2,%3};"
        : "+f"(c[0]), "+f"(c[1]), "+f"(c[2]), "+f"(c[3])
        : "r"(a[0]), "r"(a[1]), "r"(a[2]), "r"(a[3]), "r"(b0), "r"(b1));
}
__device__ __forceinline__ void lds64(uint32_t& r0, uint32_t& r1, uint32_t a) {
    asm volatile("ld.shared.v2.u32 {%0,%1}, [%2];" : "=r"(r0), "=r"(r1) : "r"(a));
}

// ================= weight shuffle kernel (fragment order) ==================
// chunk layout: flat idx o = (((s*32 + nb)*32 + lane)*2 + r)*2 + e
//   n = nb*8 + lane/4,  k_in_chunk = s*16 + (lane%4)*2 + r*8 + e
__global__ void conv_kernel(const float* __restrict__ W, int Kreal, int chunk0) {
    extern __shared__ float ws[];     // [64][257]
    const int lc = blockIdx.x, tid = threadIdx.x;
    for (int i = 0; i < 64; i++) {
        int k = lc * 64 + i;
        ws[i * 257 + tid] = (k < Kreal) ? W[(size_t)k * 256 + tid] : 0.f;
    }
    __syncthreads();
    const size_t base = (size_t)(chunk0 + lc) * CHUNK_ELEMS;
    for (int o = tid; o < CHUNK_ELEMS; o += 256) {
        int e = o & 1, r = (o >> 1) & 1, ln = (o >> 2) & 31;
        int nb = (o >> 7) & 31, s = (o >> 12) & 3;
        int n = nb * 8 + (ln >> 2);
        int kic = s * 16 + (ln & 3) * 2 + r * 8 + e;
        float w = ws[kic * 257 + n];
        __nv_bfloat16 h = __float2bfloat16(w);
        g_Bh[base + o] = h;
        g_Bl[base + o] = __float2bfloat16(w - __bfloat162float(h));
    }
}

// ===================== per-chunk MMA (one k64 chunk) =======================
// warp grid: wm in [0,8) -> 16-row M tile;  wn in [0,2) -> 128-col N tile
template<int HP, int HSTR>
__device__ __forceinline__ void chunk_mma(
    const float* __restrict__ xsm, const float* __restrict__ hb,
    uint32_t bbase, int lch, int KR, int lane, int wm, int wn,
    float (&acc)[16][4])
{
    const int q2 = (lane & 3) * 2;
    const int rb = wm * 16 + (lane >> 2);
#pragma unroll 1
    for (int s = 0; s < 4; s++) {
        const int kb = lch * 64 + s * 16;
        const int kk[4] = { kb + q2, kb + q2 + 1, kb + q2 + 8, kb + q2 + 9 };

        uint32_t ahi[4], alo[4];
        {
            float av[2][4];
#pragma unroll
            for (int ki = 0; ki < 4; ki++) {
                const int ff = kk[ki] / HP, cc = kk[ki] % HP;
                float a0 = xsm[rb * XS + ff] * hb[rb * HSTR + cc];
                float a1 = xsm[(rb + 8) * XS + ff] * hb[(rb + 8) * HSTR + cc];
                if (kk[ki] >= KR) { a0 = 0.f; a1 = 0.f; }
                av[0][ki] = a0; av[1][ki] = a1;
            }
#pragma unroll
            for (int h = 0; h < 2; h++) {
                __nv_bfloat162 p01 = __floats2bfloat162_rn(av[h][0], av[h][1]);
                __nv_bfloat162 p23 = __floats2bfloat162_rn(av[h][2], av[h][3]);
                __nv_bfloat162 q01 = __floats2bfloat162_rn(
                    av[h][0] - __low2float(p01), av[h][1] - __high2float(p01));
                __nv_bfloat162 q23 = __floats2bfloat162_rn(
                    av[h][2] - __low2float(p23), av[h][3] - __high2float(p23));
                ahi[h]     = *(uint32_t*)&p01;
                ahi[2 + h] = *(uint32_t*)&p23;
                alo[h]     = *(uint32_t*)&q01;
                alo[2 + h] = *(uint32_t*)&q23;
            }
        }

        const uint32_t rowa = bbase + (((s * 32 + wn * 16) * 32) + lane) * 8;
#pragma unroll
        for (int j = 0; j < 16; j++) {
            uint32_t bh0, bh1, bl0, bl1;
            lds64(bh0, bh1, rowa + j * 256);
            lds64(bl0, bl1, rowa + j * 256 + 32768);
            mma_bf16(acc[j], ahi, bh0, bh1);
            mma_bf16(acc[j], ahi, bl0, bl1);
            mma_bf16(acc[j], alo, bh0, bh1);
        }
    }
}

// ============================ main fused kernel ============================
__global__ void __launch_bounds__(NT, 1)
cin_mma(const float* __restrict__ x,
        const float* __restrict__ b0, const float* __restrict__ b1,
        const float* __restrict__ b2,
        const float* __restrict__ fcw, const float* __restrict__ fcb,
        float* __restrict__ out)
{
    extern __shared__ char sm[];
    const uint32_t smb = s2u(sm);
    float* xsm = (float*)(sm + SM_X);
    float* hsm = (float*)(sm + SM_H);
    float* rowsum = (float*)(sm + SM_RS);

    const int tid = threadIdx.x, wid = tid >> 5, lane = tid & 31;
    const int wn = wid & 1, wm = wid >> 1;
    const int m0 = blockIdx.x * MT;

    if (tid < MT) rowsum[tid] = 0.f;

    // stage x tile: xsm[ml][f] = x[b, f, d];  m = m0+ml, b = m/32, d = m%32
    for (int i = tid; i < F_DIM * MT; i += NT) {
        int f = i >> 7, ml = i & 127, m = m0 + ml;
        xsm[ml * XS + f] = x[((size_t)(m >> 5) * F_DIM + f) * 32 + (m & 31)];
    }

    auto stage = [&](int gch, int q) {
        const __nv_bfloat16* bh = g_Bh + (size_t)gch * CHUNK_ELEMS;
        const __nv_bfloat16* bl = g_Bl + (size_t)gch * CHUNK_ELEMS;
        const uint32_t dst = smb + SM_B + q * B_BUF;
        for (int i = tid; i < 2048; i += NT) {
            cp16(dst + i * 16,         bh + i * 8);
            cp16(dst + 32768 + i * 16, bl + i * 8);
        }
    };

    float acc[16][4];
    int gch = 0;
    stage(0, 0);
    CP_COMMIT();

    for (int L = 0; L < 3; L++) {
        const int nch = (L == 0) ? NCH0 : NCH12;
        const int KR  = (L == 0) ? K0_REAL : K12;
#pragma unroll
        for (int j = 0; j < 16; j++)
#pragma unroll
            for (int r = 0; r < 4; r++) acc[j][r] = 0.f;

        for (int lch = 0; lch < nch; lch++, gch++) {
            const int q = gch & 1;
            if (gch + 1 < NCHT) stage(gch + 1, q ^ 1);
            CP_COMMIT();
            CP_WAIT1();
            __syncthreads();
            const uint32_t bbase = smb + SM_B + q * B_BUF;
            if (L == 0)
                chunk_mma<F_DIM, XS>(xsm, xsm, bbase, lch, KR, lane, wm, wn, acc);
            else
                chunk_mma<128, HS>(xsm, hsm, bbase, lch, KR, lane, wm, wn, acc);
            __syncthreads();
        }

        // ---- layer epilogue: bias+relu, h feedback, fc_w partial dots ----
        const float* bias = (L == 0) ? b0 : (L == 1) ? b1 : b2;
        const float* fa   = (L == 0) ? (fcw - 128) : (L == 1) ? fcw : (fcw + 256);
        const int cs      = (L < 2) ? 128 : 0;
        const bool wh     = (L < 2);
        float rs[2] = {0.f, 0.f};
#pragma unroll
        for (int j = 0; j < 16; j++)
#pragma unroll
            for (int r = 0; r < 4; r++) {
                int row = wm * 16 + (lane >> 2) + ((r >> 1) << 3);
                int col = wn * 128 + j * 8 + ((lane & 3) << 1) + (r & 1);
                float v = fmaxf(acc[j][r] + __ldg(&bias[col]), 0.f);
                if (wh && wn == 0) hsm[row * HS + col] = v;
                if (col >= cs) rs[r >> 1] += v * __ldg(&fa[col]);
            }
#pragma unroll
        for (int i = 0; i < 2; i++) {
            float v = rs[i];
            v += __shfl_xor_sync(0xffffffffu, v, 1);
            v += __shfl_xor_sync(0xffffffffu, v, 2);
            if ((lane & 3) == 0) {
                int row = wm * 16 + (lane >> 2) + (i << 3);
                atomicAdd(&rowsum[row], v);
            }
        }
        __syncthreads();
    }

    // final: each 32-row group (= one batch element) reduces to one scalar
    if (tid < MT) {
        float v = rowsum[tid];
#pragma unroll
        for (int o = 16; o; o >>= 1) v += __shfl_xor_sync(0xffffffffu, v, o);
        if ((tid & 31) == 0) out[blockIdx.x * 4 + wid] = v + fcb[0];
    }
}

// ============================ launch =======================================
extern "C" void kernel_launch(void* const* d_in, const int* in_sizes, int n_in,
                              void* d_out, int out_size)
{
    const float* x   = (const float*)d_in[0];
    const float* W0  = (const float*)d_in[1];
    const float* b0  = (const float*)d_in[2];
    const float* W1  = (const float*)d_in[3];
    const float* b1  = (const float*)d_in[4];
    const float* W2  = (const float*)d_in[5];
    const float* b2  = (const float*)d_in[6];
    const float* fcw = (const float*)d_in[7];
    const float* fcb = (const float*)d_in[8];
    float* out = (float*)d_out;

    // weight shuffle/split (every launch; idempotent, graph-capturable)
    const int conv_smem = 64 * 257 * 4;
    cudaFuncSetAttribute(conv_kernel, cudaFuncAttributeMaxDynamicSharedMemorySize, conv_smem);
    conv_kernel<<<NCH0,  256, conv_smem>>>(W0, K0_REAL, 0);
    conv_kernel<<<NCH12, 256, conv_smem>>>(W1, K12, NCH0);
    conv_kernel<<<NCH12, 256, conv_smem>>>(W2, K12, NCH0 + NCH12);

    int B = in_sizes[0] / (F_DIM * 32);      // 1024
    int grid = (B * 32) / MT;                // 256

    cudaFuncSetAttribute(cin_mma, cudaFuncAttributeMaxDynamicSharedMemorySize, SM_TOT);
    cin_mma<<<grid, NT, SM_TOT>>>(x, b0, b1, b2, fcw, fcb, out);
}

// round 7
// speedup vs baseline: 1.0297x; 1.0297x over previous
#include <cuda_runtime.h>
#include <cuda_bf16.h>
#include <stdint.h>

// ============================ problem constants ============================
#define F_DIM   39
#define NT      256
#define MT      128              // rows (b,d) per CTA
#define NCH0    24               // layer0 k64 chunks (K padded 1521->1536)
#define NCH12   78               // layer1/2 chunks (4992 exact)
#define NCHT    (NCH0 + 2*NCH12) // 180
#define K0_REAL 1521
#define K12     4992
#define CHUNK_ELEMS 16384        // 64 k x 256 n (counted in bf16 elems x2 for hi+lo)

// weights pre-shuffled into per-lane mma fragment order, hi/lo interleaved:
// 16B unit u = ((s*32 + jg)*32 + lane) holds {bh0,bh1,bl0,bl1}
//   n  = jg*8 + lane/4
//   k_in_chunk = s*16 + (lane%4)*2 + r*8 + e   (r,e index within regs)
__device__ __align__(256) uint4 g_B[(size_t)NCHT * 4096];

// ============================ smem layout (bytes) ==========================
#define B_BUF  65536                     // per buffer (hi+lo interleaved)
#define SM_B   0
#define SM_X   (2*B_BUF)                 // 131072 : x fp32 [128][XS]
#define XS     41
#define SM_H   (SM_X + 128*XS*4)         // 152064 : h fp32 [128][HS]
#define HS     132
#define SM_RS  (SM_H + 128*HS*4)         // 219648 : rowsum[128]
#define SM_TOT (SM_RS + 512)             // 220160

// ============================ helpers ======================================
__device__ __forceinline__ uint32_t s2u(const void* p) {
    uint32_t a;
    asm("{ .reg .u64 t; cvta.to.shared.u64 t, %1; cvt.u32.u64 %0, t; }" : "=r"(a) : "l"(p));
    return a;
}
__device__ __forceinline__ void cp16(uint32_t s, const void* g) {
    asm volatile("cp.async.cg.shared.global [%0], [%1], 16;" :: "r"(s), "l"(g));
}
#define CP_COMMIT() asm volatile("cp.async.commit_group;")
#define CP_WAIT1()  asm volatile("cp.async.wait_group 1;" ::: "memory")

__device__ __forceinline__ void mma_bf16(float* c, const uint32_t* a, uint32_t b0, uint32_t b1) {
    asm volatile("mma.sync.aligned.m16n8k16.row.col.f32.bf16.bf16.f32 "
        "{%0,%1,%2,%3}, {%4,%5,%6,%7}, {%8,%9}, {%0,%1,%2,%3};"
        : "+f"(c[0]), "+f"(c[1]), "+f"(c[2]), "+f"(c[3])
        : "r"(a[0]), "r"(a[1]), "r"(a[2]), "r"(a[3]), "r"(b0), "r"(b1));
}
__device__ __forceinline__ void lds128(uint32_t& r0, uint32_t& r1, uint32_t& r2, uint32_t& r3, uint32_t a) {
    asm volatile("ld.shared.v4.u32 {%0,%1,%2,%3}, [%4];"
        : "=r"(r0), "=r"(r1), "=r"(r2), "=r"(r3) : "r"(a));
}

// ================= weight shuffle kernel (fragment order) ==================
__global__ void conv_kernel(const float* __restrict__ W, int Kreal, int chunk0) {
    extern __shared__ float ws[];     // [64][257]
    const int lc = blockIdx.x, tid = threadIdx.x;
    for (int i = 0; i < 64; i++) {
        int k = lc * 64 + i;
        ws[i * 257 + tid] = (k < Kreal) ? W[(size_t)k * 256 + tid] : 0.f;
    }
    __syncthreads();
    const size_t base = (size_t)(chunk0 + lc) * 4096;
    // one 16B unit per iteration: u in [0,4096)
    for (int u = tid; u < 4096; u += 256) {
        int lane = u & 31, jg = (u >> 5) & 31, s = (u >> 10) & 3;
        int n = jg * 8 + (lane >> 2);
        int kbase = s * 16 + (lane & 3) * 2;
        uint32_t hp[2], lp[2];
#pragma unroll
        for (int r = 0; r < 2; r++) {
            float w0 = ws[(kbase + r * 8)     * 257 + n];
            float w1 = ws[(kbase + r * 8 + 1) * 257 + n];
            __nv_bfloat162 hh = __floats2bfloat162_rn(w0, w1);
            __nv_bfloat162 ll = __floats2bfloat162_rn(
                w0 - __low2float(hh), w1 - __high2float(hh));
            hp[r] = *(uint32_t*)&hh;
            lp[r] = *(uint32_t*)&ll;
        }
        g_B[base + u] = make_uint4(hp[0], hp[1], lp[0], lp[1]);
    }
}

// =================== per-chunk A fragment generation =======================
// warp grid: wm in [0,4) -> 32-row M tile (2 mt x 16);  wn in [0,2)
template<int HP, int HSTR>
__device__ __forceinline__ void gen_A(
    const float* __restrict__ xsm, const float* __restrict__ hb,
    int lch, int KR, int lane, int wm,
    uint32_t (&ahi)[4][2][4], uint32_t (&alo)[4][2][4])
{
    const int q2 = (lane & 3) * 2;
    const int rb = wm * 32 + (lane >> 2);
#pragma unroll
    for (int s = 0; s < 4; s++) {
        const int kb = lch * 64 + s * 16;
        const int kk[4] = { kb + q2, kb + q2 + 1, kb + q2 + 8, kb + q2 + 9 };
#pragma unroll
        for (int mt = 0; mt < 2; mt++) {
            float av[2][4];
#pragma unroll
            for (int ki = 0; ki < 4; ki++) {
                const int ff = kk[ki] / HP, cc = kk[ki] % HP;
                const int m_lo = rb + mt * 16, m_hi = m_lo + 8;
                float a0 = xsm[m_lo * XS + ff] * hb[m_lo * HSTR + cc];
                float a1 = xsm[m_hi * XS + ff] * hb[m_hi * HSTR + cc];
                if (kk[ki] >= KR) { a0 = 0.f; a1 = 0.f; }
                av[0][ki] = a0; av[1][ki] = a1;
            }
#pragma unroll
            for (int h = 0; h < 2; h++) {
                __nv_bfloat162 p01 = __floats2bfloat162_rn(av[h][0], av[h][1]);
                __nv_bfloat162 p23 = __floats2bfloat162_rn(av[h][2], av[h][3]);
                __nv_bfloat162 q01 = __floats2bfloat162_rn(
                    av[h][0] - __low2float(p01), av[h][1] - __high2float(p01));
                __nv_bfloat162 q23 = __floats2bfloat162_rn(
                    av[h][2] - __low2float(p23), av[h][3] - __high2float(p23));
                ahi[s][mt][h]     = *(uint32_t*)&p01;
                ahi[s][mt][2 + h] = *(uint32_t*)&p23;
                alo[s][mt][h]     = *(uint32_t*)&q01;
                alo[s][mt][2 + h] = *(uint32_t*)&q23;
            }
        }
    }
}

// ============================ main fused kernel ============================
__global__ void __launch_bounds__(NT, 1)
cin_mma(const float* __restrict__ x,
        const float* __restrict__ b0, const float* __restrict__ b1,
        const float* __restrict__ b2,
        const float* __restrict__ fcw, const float* __restrict__ fcb,
        float* __restrict__ out)
{
    extern __shared__ char sm[];
    const uint32_t smb = s2u(sm);
    float* xsm = (float*)(sm + SM_X);
    float* hsm = (float*)(sm + SM_H);
    float* rowsum = (float*)(sm + SM_RS);

    const int tid = threadIdx.x, wid = tid >> 5, lane = tid & 31;
    const int wm = wid & 3, wn = wid >> 2;
    const int m0 = blockIdx.x * MT;

    if (tid < MT) rowsum[tid] = 0.f;

    // stage x tile: xsm[ml][f] = x[b, f, d];  m = m0+ml, b = m/32, d = m%32
    for (int i = tid; i < F_DIM * MT; i += NT) {
        int f = i >> 7, ml = i & 127, m = m0 + ml;
        xsm[ml * XS + f] = x[((size_t)(m >> 5) * F_DIM + f) * 32 + (m & 31)];
    }

    auto stage = [&](int gch, int q) {
        const uint4* src = g_B + (size_t)gch * 4096;
        const uint32_t dst = smb + SM_B + q * B_BUF;
        for (int i = tid; i < 4096; i += NT)
            cp16(dst + i * 16, src + i);
    };

    float acc[2][16][4];
    uint32_t ahi[4][2][4], alo[4][2][4];
    int gch = 0;
    stage(0, 0);
    CP_COMMIT();

    for (int L = 0; L < 3; L++) {
        const int nch = (L == 0) ? NCH0 : NCH12;
        const int KR  = (L == 0) ? K0_REAL : K12;
#pragma unroll
        for (int mt = 0; mt < 2; mt++)
#pragma unroll
            for (int j = 0; j < 16; j++)
#pragma unroll
                for (int r = 0; r < 4; r++) acc[mt][j][r] = 0.f;

        for (int lch = 0; lch < nch; lch++, gch++) {
            const int q = gch & 1;
            if (gch + 1 < NCHT) stage(gch + 1, q ^ 1);
            CP_COMMIT();

            // A-gen overlaps the in-flight cp.async for the *current* buffer
            if (L == 0)
                gen_A<F_DIM, XS>(xsm, xsm, lch, KR, lane, wm, ahi, alo);
            else
                gen_A<128, HS>(xsm, hsm, lch, KR, lane, wm, ahi, alo);

            CP_WAIT1();
            __syncthreads();

            // pure LDS+MMA stream
            const uint32_t bbase = smb + SM_B + q * B_BUF + (uint32_t)(wn * 16 * 32 + lane) * 16;
#pragma unroll
            for (int s = 0; s < 4; s++) {
                const uint32_t rowa = bbase + s * 16384;
#pragma unroll
                for (int j = 0; j < 16; j++) {
                    uint32_t bh0, bh1, bl0, bl1;
                    lds128(bh0, bh1, bl0, bl1, rowa + j * 512);
                    mma_bf16(acc[0][j], ahi[s][0], bh0, bh1);
                    mma_bf16(acc[1][j], ahi[s][1], bh0, bh1);
                    mma_bf16(acc[0][j], ahi[s][0], bl0, bl1);
                    mma_bf16(acc[1][j], ahi[s][1], bl0, bl1);
                    mma_bf16(acc[0][j], alo[s][0], bh0, bh1);
                    mma_bf16(acc[1][j], alo[s][1], bh0, bh1);
                }
            }
            __syncthreads();
        }

        // ---- layer epilogue: bias+relu, h feedback, fc_w partial dots ----
        const float* bias = (L == 0) ? b0 : (L == 1) ? b1 : b2;
        const float* fa   = (L == 0) ? (fcw - 128) : (L == 1) ? fcw : (fcw + 256);
        const int cs      = (L < 2) ? 128 : 0;
        const bool wh     = (L < 2);
        float rs[4] = {0.f, 0.f, 0.f, 0.f};
#pragma unroll
        for (int mt = 0; mt < 2; mt++)
#pragma unroll
            for (int j = 0; j < 16; j++)
#pragma unroll
                for (int r = 0; r < 4; r++) {
                    int row = wm * 32 + mt * 16 + (lane >> 2) + ((r >> 1) << 3);
                    int col = wn * 128 + j * 8 + ((lane & 3) << 1) + (r & 1);
                    float v = fmaxf(acc[mt][j][r] + __ldg(&bias[col]), 0.f);
                    if (wh && wn == 0) hsm[row * HS + col] = v;
                    if (col >= cs) rs[mt * 2 + (r >> 1)] += v * __ldg(&fa[col]);
                }
#pragma unroll
        for (int i = 0; i < 4; i++) {
            float v = rs[i];
            v += __shfl_xor_sync(0xffffffffu, v, 1);
            v += __shfl_xor_sync(0xffffffffu, v, 2);
            if ((lane & 3) == 0) {
                int row = wm * 32 + (i >> 1) * 16 + (lane >> 2) + ((i & 1) << 3);
                atomicAdd(&rowsum[row], v);
            }
        }
        __syncthreads();
    }

    // final: each 32-row group (= one batch element) reduces to one scalar
    if (tid < MT) {
        float v = rowsum[tid];
#pragma unroll
        for (int o = 16; o; o >>= 1) v += __shfl_xor_sync(0xffffffffu, v, o);
        if ((tid & 31) == 0) out[blockIdx.x * 4 + wid] = v + fcb[0];
    }
}

// ============================ launch =======================================
extern "C" void kernel_launch(void* const* d_in, const int* in_sizes, int n_in,
                              void* d_out, int out_size)
{
    const float* x   = (const float*)d_in[0];
    const float* W0  = (const float*)d_in[1];
    const float* b0  = (const float*)d_in[2];
    const float* W1  = (const float*)d_in[3];
    const float* b1  = (const float*)d_in[4];
    const float* W2  = (const float*)d_in[5];
    const float* b2  = (const float*)d_in[6];
    const float* fcw = (const float*)d_in[7];
    const float* fcb = (const float*)d_in[8];
    float* out = (float*)d_out;

    // weight shuffle/split (every launch; idempotent, graph-capturable)
    const int conv_smem = 64 * 257 * 4;
    cudaFuncSetAttribute(conv_kernel, cudaFuncAttributeMaxDynamicSharedMemorySize, conv_smem);
    conv_kernel<<<NCH0,  256, conv_smem>>>(W0, K0_REAL, 0);
    conv_kernel<<<NCH12, 256, conv_smem>>>(W1, K12, NCH0);
    conv_kernel<<<NCH12, 256, conv_smem>>>(W2, K12, NCH0 + NCH12);

    int B = in_sizes[0] / (F_DIM * 32);      // 1024
    int grid = (B * 32) / MT;                // 256

    cudaFuncSetAttribute(cin_mma, cudaFuncAttributeMaxDynamicSharedMemorySize, SM_TOT);
    cin_mma<<<grid, NT, SM_TOT>>>(x, b0, b1, b2, fcw, fcb, out);
}

// round 8
// speedup vs baseline: 1.0645x; 1.0338x over previous
#include <cuda_runtime.h>
#include <cuda_bf16.h>
#include <stdint.h>

// ============================ problem constants ============================
#define F_DIM   39
#define NT      256
#define MT      128              // rows (b,d) per CTA
#define NCH0    24               // layer0 k64 chunks (K padded 1521->1536)
#define NCH12   78               // layer1/2 chunks (4992 exact)
#define NCHT    (NCH0 + 2*NCH12) // 180
#define K0_REAL 1521
#define K12     4992

// weights pre-shuffled into per-lane mma fragment order, hi/lo interleaved:
// 16B unit u = ((s*32 + jg)*32 + lane) holds {bh0,bh1,bl0,bl1}
//   n = jg*8 + lane/4,  k_in_chunk = s*16 + (lane%4)*2 + r*8 + e
__device__ __align__(256) uint4 g_B[(size_t)NCHT * 4096];

// ============================ smem layout (bytes) ==========================
#define B_BUF  65536                     // per buffer (hi+lo interleaved)
#define SM_B   0
#define SM_X   (2*B_BUF)                 // 131072 : x fp32 [128][XS]
#define XS     41
#define SM_H   (SM_X + 128*XS*4)         // 152064 : h fp32 [128][HS]
#define HS     132
#define SM_RS  (SM_H + 128*HS*4)         // 219648 : rowsum[128]
#define SM_TOT (SM_RS + 512)             // 220160

// ============================ helpers ======================================
__device__ __forceinline__ uint32_t s2u(const void* p) {
    uint32_t a;
    asm("{ .reg .u64 t; cvta.to.shared.u64 t, %1; cvt.u32.u64 %0, t; }" : "=r"(a) : "l"(p));
    return a;
}
__device__ __forceinline__ void cp16(uint32_t s, const void* g) {
    asm volatile("cp.async.cg.shared.global [%0], [%1], 16;" :: "r"(s), "l"(g));
}
#define CP_COMMIT() asm volatile("cp.async.commit_group;")
#define CP_WAIT1()  asm volatile("cp.async.wait_group 1;" ::: "memory")

__device__ __forceinline__ void mma_bf16(float* c, const uint32_t* a, uint32_t b0, uint32_t b1) {
    asm volatile("mma.sync.aligned.m16n8k16.row.col.f32.bf16.bf16.f32 "
        "{%0,%1,%2,%3}, {%4,%5,%6,%7}, {%8,%9}, {%0,%1,%2,%3};"
        : "+f"(c[0]), "+f"(c[1]), "+f"(c[2]), "+f"(c[3])
        : "r"(a[0]), "r"(a[1]), "r"(a[2]), "r"(a[3]), "r"(b0), "r"(b1));
}
__device__ __forceinline__ void lds128(uint32_t& r0, uint32_t& r1, uint32_t& r2, uint32_t& r3, uint32_t a) {
    asm volatile("ld.shared.v4.u32 {%0,%1,%2,%3}, [%4];"
        : "=r"(r0), "=r"(r1), "=r"(r2), "=r"(r3) : "r"(a));
}

// ================= weight shuffle kernel (fragment order) ==================
__global__ void conv_kernel(const float* __restrict__ W, int Kreal, int chunk0) {
    extern __shared__ float ws[];     // [64][257]
    const int lc = blockIdx.x, tid = threadIdx.x;
    for (int i = 0; i < 64; i++) {
        int k = lc * 64 + i;
        ws[i * 257 + tid] = (k < Kreal) ? W[(size_t)k * 256 + tid] : 0.f;
    }
    __syncthreads();
    const size_t base = (size_t)(chunk0 + lc) * 4096;
    for (int u = tid; u < 4096; u += 256) {
        int lane = u & 31, jg = (u >> 5) & 31, s = (u >> 10) & 3;
        int n = jg * 8 + (lane >> 2);
        int kbase = s * 16 + (lane & 3) * 2;
        uint32_t hp[2], lp[2];
#pragma unroll
        for (int r = 0; r < 2; r++) {
            float w0 = ws[(kbase + r * 8)     * 257 + n];
            float w1 = ws[(kbase + r * 8 + 1) * 257 + n];
            __nv_bfloat162 hh = __floats2bfloat162_rn(w0, w1);
            __nv_bfloat162 ll = __floats2bfloat162_rn(
                w0 - __low2float(hh), w1 - __high2float(hh));
            hp[r] = *(uint32_t*)&hh;
            lp[r] = *(uint32_t*)&ll;
        }
        g_B[base + u] = make_uint4(hp[0], hp[1], lp[0], lp[1]);
    }
}

// ===================== per-chunk MMA (one k64 chunk) =======================
// warp grid: wm in [0,4) -> 32-row M tile (2 mt x 16);  wn in [0,2) -> 128 cols
template<int HP, int HSTR>
__device__ __forceinline__ void chunk_mma(
    const float* __restrict__ xsm, const float* __restrict__ hb,
    uint32_t bbase, int lch, int KR, int lane, int wm,
    float (&acc)[2][16][4])
{
    const int q2 = (lane & 3) * 2;
    const int rb = wm * 32 + (lane >> 2);
#pragma unroll 1
    for (int s = 0; s < 4; s++) {
        // ---- A fragments for this k16 slice ----
        const int kb = lch * 64 + s * 16;
        const int kk[4] = { kb + q2, kb + q2 + 1, kb + q2 + 8, kb + q2 + 9 };
        uint32_t ahi[2][4], alo[2][4];
#pragma unroll
        for (int mt = 0; mt < 2; mt++) {
            float av[2][4];
#pragma unroll
            for (int ki = 0; ki < 4; ki++) {
                const int ff = kk[ki] / HP, cc = kk[ki] % HP;
                const int m_lo = rb + mt * 16, m_hi = m_lo + 8;
                float a0 = xsm[m_lo * XS + ff] * hb[m_lo * HSTR + cc];
                float a1 = xsm[m_hi * XS + ff] * hb[m_hi * HSTR + cc];
                if (kk[ki] >= KR) { a0 = 0.f; a1 = 0.f; }
                av[0][ki] = a0; av[1][ki] = a1;
            }
#pragma unroll
            for (int h = 0; h < 2; h++) {
                __nv_bfloat162 p01 = __floats2bfloat162_rn(av[h][0], av[h][1]);
                __nv_bfloat162 p23 = __floats2bfloat162_rn(av[h][2], av[h][3]);
                __nv_bfloat162 q01 = __floats2bfloat162_rn(
                    av[h][0] - __low2float(p01), av[h][1] - __high2float(p01));
                __nv_bfloat162 q23 = __floats2bfloat162_rn(
                    av[h][2] - __low2float(p23), av[h][3] - __high2float(p23));
                ahi[mt][h]     = *(uint32_t*)&p01;
                ahi[mt][2 + h] = *(uint32_t*)&p23;
                alo[mt][h]     = *(uint32_t*)&q01;
                alo[mt][2 + h] = *(uint32_t*)&q23;
            }
        }

        // ---- j in groups of 4: term-major issue, acc reuse distance 8 ----
        const uint32_t rowa = bbase + s * 16384;
#pragma unroll
        for (int jg = 0; jg < 4; jg++) {
            uint32_t bh[4][2], bl[4][2];
#pragma unroll
            for (int j4 = 0; j4 < 4; j4++)
                lds128(bh[j4][0], bh[j4][1], bl[j4][0], bl[j4][1],
                       rowa + (jg * 4 + j4) * 512);
            float (*ag)[16][4] = &acc[0];
            // term 1: Ah * Wh  (8 independent HMMAs)
#pragma unroll
            for (int j4 = 0; j4 < 4; j4++) {
                mma_bf16(ag[0][jg * 4 + j4], ahi[0], bh[j4][0], bh[j4][1]);
                mma_bf16(ag[1][jg * 4 + j4], ahi[1], bh[j4][0], bh[j4][1]);
            }
            // term 2: Ah * Wl
#pragma unroll
            for (int j4 = 0; j4 < 4; j4++) {
                mma_bf16(ag[0][jg * 4 + j4], ahi[0], bl[j4][0], bl[j4][1]);
                mma_bf16(ag[1][jg * 4 + j4], ahi[1], bl[j4][0], bl[j4][1]);
            }
            // term 3: Al * Wh
#pragma unroll
            for (int j4 = 0; j4 < 4; j4++) {
                mma_bf16(ag[0][jg * 4 + j4], alo[0], bh[j4][0], bh[j4][1]);
                mma_bf16(ag[1][jg * 4 + j4], alo[1], bh[j4][0], bh[j4][1]);
            }
        }
    }
}

// ============================ main fused kernel ============================
__global__ void __launch_bounds__(NT, 1)
cin_mma(const float* __restrict__ x,
        const float* __restrict__ b0, const float* __restrict__ b1,
        const float* __restrict__ b2,
        const float* __restrict__ fcw, const float* __restrict__ fcb,
        float* __restrict__ out)
{
    extern __shared__ char sm[];
    const uint32_t smb = s2u(sm);
    float* xsm = (float*)(sm + SM_X);
    float* hsm = (float*)(sm + SM_H);
    float* rowsum = (float*)(sm + SM_RS);

    const int tid = threadIdx.x, wid = tid >> 5, lane = tid & 31;
    const int wm = wid & 3, wn = wid >> 2;
    const int m0 = blockIdx.x * MT;

    if (tid < MT) rowsum[tid] = 0.f;

    // stage x tile: xsm[ml][f] = x[b, f, d];  m = m0+ml, b = m/32, d = m%32
    for (int i = tid; i < F_DIM * MT; i += NT) {
        int f = i >> 7, ml = i & 127, m = m0 + ml;
        xsm[ml * XS + f] = x[((size_t)(m >> 5) * F_DIM + f) * 32 + (m & 31)];
    }

    auto stage = [&](int gch, int q) {
        const uint4* src = g_B + (size_t)gch * 4096;
        const uint32_t dst = smb + SM_B + q * B_BUF;
        for (int i = tid; i < 4096; i += NT)
            cp16(dst + i * 16, src + i);
    };

    float acc[2][16][4];
    int gch = 0;
    stage(0, 0);
    CP_COMMIT();

    for (int L = 0; L < 3; L++) {
        const int nch = (L == 0) ? NCH0 : NCH12;
        const int KR  = (L == 0) ? K0_REAL : K12;
#pragma unroll
        for (int mt = 0; mt < 2; mt++)
#pragma unroll
            for (int j = 0; j < 16; j++)
#pragma unroll
                for (int r = 0; r < 4; r++) acc[mt][j][r] = 0.f;

        for (int lch = 0; lch < nch; lch++, gch++) {
            const int q = gch & 1;
            if (gch + 1 < NCHT) stage(gch + 1, q ^ 1);
            CP_COMMIT();
            CP_WAIT1();
            __syncthreads();
            const uint32_t bbase = smb + SM_B + q * B_BUF
                                 + (uint32_t)(wn * 16 * 32 + lane) * 16;
            if (L == 0)
                chunk_mma<F_DIM, XS>(xsm, xsm, bbase, lch, KR, lane, wm, acc);
            else
                chunk_mma<128, HS>(xsm, hsm, bbase, lch, KR, lane, wm, acc);
            __syncthreads();
        }

        // ---- layer epilogue: bias+relu, h feedback, fc_w partial dots ----
        const float* bias = (L == 0) ? b0 : (L == 1) ? b1 : b2;
        const float* fa   = (L == 0) ? (fcw - 128) : (L == 1) ? fcw : (fcw + 256);
        const int cs      = (L < 2) ? 128 : 0;
        const bool wh     = (L < 2);
        float rs[4] = {0.f, 0.f, 0.f, 0.f};
#pragma unroll
        for (int mt = 0; mt < 2; mt++)
#pragma unroll
            for (int j = 0; j < 16; j++)
#pragma unroll
                for (int r = 0; r < 4; r++) {
                    int row = wm * 32 + mt * 16 + (lane >> 2) + ((r >> 1) << 3);
                    int col = wn * 128 + j * 8 + ((lane & 3) << 1) + (r & 1);
                    float v = fmaxf(acc[mt][j][r] + __ldg(&bias[col]), 0.f);
                    if (wh && wn == 0) hsm[row * HS + col] = v;
                    if (col >= cs) rs[mt * 2 + (r >> 1)] += v * __ldg(&fa[col]);
                }
#pragma unroll
        for (int i = 0; i < 4; i++) {
            float v = rs[i];
            v += __shfl_xor_sync(0xffffffffu, v, 1);
            v += __shfl_xor_sync(0xffffffffu, v, 2);
            if ((lane & 3) == 0) {
                int row = wm * 32 + (i >> 1) * 16 + (lane >> 2) + ((i & 1) << 3);
                atomicAdd(&rowsum[row], v);
            }
        }
        __syncthreads();
    }

    // final: each 32-row group (= one batch element) reduces to one scalar
    if (tid < MT) {
        float v = rowsum[tid];
#pragma unroll
        for (int o = 16; o; o >>= 1) v += __shfl_xor_sync(0xffffffffu, v, o);
        if ((tid & 31) == 0) out[blockIdx.x * 4 + wid] = v + fcb[0];
    }
}

// ============================ launch =======================================
extern "C" void kernel_launch(void* const* d_in, const int* in_sizes, int n_in,
                              void* d_out, int out_size)
{
    const float* x   = (const float*)d_in[0];
    const float* W0  = (const float*)d_in[1];
    const float* b0  = (const float*)d_in[2];
    const float* W1  = (const float*)d_in[3];
    const float* b1  = (const float*)d_in[4];
    const float* W2  = (const float*)d_in[5];
    const float* b2  = (const float*)d_in[6];
    const float* fcw = (const float*)d_in[7];
    const float* fcb = (const float*)d_in[8];
    float* out = (float*)d_out;

    // weight shuffle/split (every launch; idempotent, graph-capturable)
    const int conv_smem = 64 * 257 * 4;
    cudaFuncSetAttribute(conv_kernel, cudaFuncAttributeMaxDynamicSharedMemorySize, conv_smem);
    conv_kernel<<<NCH0,  256, conv_smem>>>(W0, K0_REAL, 0);
    conv_kernel<<<NCH12, 256, conv_smem>>>(W1, K12, NCH0);
    conv_kernel<<<NCH12, 256, conv_smem>>>(W2, K12, NCH0 + NCH12);

    int B = in_sizes[0] / (F_DIM * 32);      // 1024
    int grid = (B * 32) / MT;                // 256

    cudaFuncSetAttribute(cin_mma, cudaFuncAttributeMaxDynamicSharedMemorySize, SM_TOT);
    cin_mma<<<grid, NT, SM_TOT>>>(x, b0, b1, b2, fcw, fcb, out);
}

// round 9
// speedup vs baseline: 1.4413x; 1.3540x over previous
#include <cuda_runtime.h>
#include <cuda_fp16.h>
#include <stdint.h>

// ============================ problem constants ============================
#define F_DIM   39
#define NT      256
#define MT      128              // rows (b,d) per CTA
#define NCH0    24               // layer0 k64 chunks (K padded 1521->1536)
#define NCH12   78               // layer1/2 chunks (4992 exact)
#define NCHT    (NCH0 + 2*NCH12) // 180
#define K0_REAL 1521
#define K12     4992

// weights pre-shuffled into per-lane mma fragment order, fp16 hi/lo interleaved:
// 16B unit u = ((s*32 + jg)*32 + lane) holds {wh0,wh1,wl0,wl1}
//   n = jg*8 + lane/4,  k_in_chunk = s*16 + (lane%4)*2 + r*8 + e
__device__ __align__(256) uint4 g_B[(size_t)NCHT * 4096];

// ============================ smem layout (bytes) ==========================
#define B_BUF  65536                     // per buffer (hi+lo interleaved)
#define SM_B   0
#define SM_X   (2*B_BUF)                 // 131072 : x fp32 [128][XS]
#define XS     41
#define SM_H   (SM_X + 128*XS*4)         // 152064 : h fp32 [128][HS]
#define HS     132
#define SM_RS  (SM_H + 128*HS*4)         // 219648 : rowsum[128]
#define SM_TOT (SM_RS + 512)             // 220160

// ============================ helpers ======================================
__device__ __forceinline__ uint32_t s2u(const void* p) {
    uint32_t a;
    asm("{ .reg .u64 t; cvta.to.shared.u64 t, %1; cvt.u32.u64 %0, t; }" : "=r"(a) : "l"(p));
    return a;
}
__device__ __forceinline__ void cp16(uint32_t s, const void* g) {
    asm volatile("cp.async.cg.shared.global [%0], [%1], 16;" :: "r"(s), "l"(g));
}
#define CP_COMMIT() asm volatile("cp.async.commit_group;")
#define CP_WAIT1()  asm volatile("cp.async.wait_group 1;" ::: "memory")

__device__ __forceinline__ void mma_f16(float* c, const uint32_t* a, uint32_t b0, uint32_t b1) {
    asm volatile("mma.sync.aligned.m16n8k16.row.col.f32.f16.f16.f32 "
        "{%0,%1,%2,%3}, {%4,%5,%6,%7}, {%8,%9}, {%0,%1,%2,%3};"
        : "+f"(c[0]), "+f"(c[1]), "+f"(c[2]), "+f"(c[3])
        : "r"(a[0]), "r"(a[1]), "r"(a[2]), "r"(a[3]), "r"(b0), "r"(b1));
}
__device__ __forceinline__ void lds128(uint32_t& r0, uint32_t& r1, uint32_t& r2, uint32_t& r3, uint32_t a) {
    asm volatile("ld.shared.v4.u32 {%0,%1,%2,%3}, [%4];"
        : "=r"(r0), "=r"(r1), "=r"(r2), "=r"(r3) : "r"(a));
}

// ================= weight shuffle kernel (fragment order) ==================
__global__ void conv_kernel(const float* __restrict__ W, int Kreal, int chunk0) {
    extern __shared__ float ws[];     // [64][257]
    const int lc = blockIdx.x, tid = threadIdx.x;
    for (int i = 0; i < 64; i++) {
        int k = lc * 64 + i;
        ws[i * 257 + tid] = (k < Kreal) ? W[(size_t)k * 256 + tid] : 0.f;
    }
    __syncthreads();
    const size_t base = (size_t)(chunk0 + lc) * 4096;
    for (int u = tid; u < 4096; u += 256) {
        int lane = u & 31, jg = (u >> 5) & 31, s = (u >> 10) & 3;
        int n = jg * 8 + (lane >> 2);
        int kbase = s * 16 + (lane & 3) * 2;
        uint32_t hp[2], lp[2];
#pragma unroll
        for (int r = 0; r < 2; r++) {
            float w0 = ws[(kbase + r * 8)     * 257 + n];
            float w1 = ws[(kbase + r * 8 + 1) * 257 + n];
            __half2 hh = __floats2half2_rn(w0, w1);
            __half2 ll = __floats2half2_rn(
                w0 - __low2float(hh), w1 - __high2float(hh));
            hp[r] = *(uint32_t*)&hh;
            lp[r] = *(uint32_t*)&ll;
        }
        g_B[base + u] = make_uint4(hp[0], hp[1], lp[0], lp[1]);
    }
}

// ===================== per-chunk MMA (one k64 chunk) =======================
// warp grid: wm in [0,4) -> 32-row M tile (2 mt x 16);  wn in [0,2) -> 128 cols
template<int HP, int HSTR>
__device__ __forceinline__ void chunk_mma(
    const float* __restrict__ xsm, const float* __restrict__ hb,
    uint32_t bbase, int lch, int KR, int lane, int wm,
    float (&acc)[2][16][4])
{
    const int q2 = (lane & 3) * 2;
    const int rb = wm * 32 + (lane >> 2);
#pragma unroll 1
    for (int s = 0; s < 4; s++) {
        // ---- A fragments (fp16, hi only) for this k16 slice ----
        const int kb = lch * 64 + s * 16;
        const int kk[4] = { kb + q2, kb + q2 + 1, kb + q2 + 8, kb + q2 + 9 };
        uint32_t ah[2][4];
#pragma unroll
        for (int mt = 0; mt < 2; mt++) {
            float av[2][4];
#pragma unroll
            for (int ki = 0; ki < 4; ki++) {
                const int ff = kk[ki] / HP, cc = kk[ki] % HP;
                const int m_lo = rb + mt * 16, m_hi = m_lo + 8;
                float a0 = xsm[m_lo * XS + ff] * hb[m_lo * HSTR + cc];
                float a1 = xsm[m_hi * XS + ff] * hb[m_hi * HSTR + cc];
                if (kk[ki] >= KR) { a0 = 0.f; a1 = 0.f; }
                av[0][ki] = a0; av[1][ki] = a1;
            }
#pragma unroll
            for (int h = 0; h < 2; h++) {
                __half2 p01 = __floats2half2_rn(av[h][0], av[h][1]);
                __half2 p23 = __floats2half2_rn(av[h][2], av[h][3]);
                ah[mt][h]     = *(uint32_t*)&p01;
                ah[mt][2 + h] = *(uint32_t*)&p23;
            }
        }

        // ---- j in groups of 4: term-major issue ----
        const uint32_t rowa = bbase + s * 16384;
#pragma unroll
        for (int jg = 0; jg < 4; jg++) {
            uint32_t bh[4][2], bl[4][2];
#pragma unroll
            for (int j4 = 0; j4 < 4; j4++)
                lds128(bh[j4][0], bh[j4][1], bl[j4][0], bl[j4][1],
                       rowa + (jg * 4 + j4) * 512);
            // term 1: Ah * Wh  (8 independent HMMAs)
#pragma unroll
            for (int j4 = 0; j4 < 4; j4++) {
                mma_f16(acc[0][jg * 4 + j4], ah[0], bh[j4][0], bh[j4][1]);
                mma_f16(acc[1][jg * 4 + j4], ah[1], bh[j4][0], bh[j4][1]);
            }
            // term 2: Ah * Wl
#pragma unroll
            for (int j4 = 0; j4 < 4; j4++) {
                mma_f16(acc[0][jg * 4 + j4], ah[0], bl[j4][0], bl[j4][1]);
                mma_f16(acc[1][jg * 4 + j4], ah[1], bl[j4][0], bl[j4][1]);
            }
        }
    }
}

// ============================ main fused kernel ============================
__global__ void __launch_bounds__(NT, 1)
cin_mma(const float* __restrict__ x,
        const float* __restrict__ b0, const float* __restrict__ b1,
        const float* __restrict__ b2,
        const float* __restrict__ fcw, const float* __restrict__ fcb,
        float* __restrict__ out)
{
    extern __shared__ char sm[];
    const uint32_t smb = s2u(sm);
    float* xsm = (float*)(sm + SM_X);
    float* hsm = (float*)(sm + SM_H);
    float* rowsum = (float*)(sm + SM_RS);

    const int tid = threadIdx.x, wid = tid >> 5, lane = tid & 31;
    const int wm = wid & 3, wn = wid >> 2;
    const int m0 = blockIdx.x * MT;

    if (tid < MT) rowsum[tid] = 0.f;

    // stage x tile: xsm[ml][f] = x[b, f, d];  m = m0+ml, b = m/32, d = m%32
    for (int i = tid; i < F_DIM * MT; i += NT) {
        int f = i >> 7, ml = i & 127, m = m0 + ml;
        xsm[ml * XS + f] = x[((size_t)(m >> 5) * F_DIM + f) * 32 + (m & 31)];
    }

    auto stage = [&](int gch, int q) {
        const uint4* src = g_B + (size_t)gch * 4096;
        const uint32_t dst = smb + SM_B + q * B_BUF;
        for (int i = tid; i < 4096; i += NT)
            cp16(dst + i * 16, src + i);
    };

    float acc[2][16][4];
    int gch = 0;
    stage(0, 0);
    CP_COMMIT();

    for (int L = 0; L < 3; L++) {
        const int nch = (L == 0) ? NCH0 : NCH12;
        const int KR  = (L == 0) ? K0_REAL : K12;
#pragma unroll
        for (int mt = 0; mt < 2; mt++)
#pragma unroll
            for (int j = 0; j < 16; j++)
#pragma unroll
                for (int r = 0; r < 4; r++) acc[mt][j][r] = 0.f;

        for (int lch = 0; lch < nch; lch++, gch++) {
            const int q = gch & 1;
            if (gch + 1 < NCHT) stage(gch + 1, q ^ 1);
            CP_COMMIT();
            CP_WAIT1();
            __syncthreads();
            const uint32_t bbase = smb + SM_B + q * B_BUF
                                 + (uint32_t)(wn * 16 * 32 + lane) * 16;
            if (L == 0)
                chunk_mma<F_DIM, XS>(xsm, xsm, bbase, lch, KR, lane, wm, acc);
            else
                chunk_mma<128, HS>(xsm, hsm, bbase, lch, KR, lane, wm, acc);
            __syncthreads();
        }

        // ---- layer epilogue: bias+relu, h feedback, fc_w partial dots ----
        const float* bias = (L == 0) ? b0 : (L == 1) ? b1 : b2;
        const float* fa   = (L == 0) ? (fcw - 128) : (L == 1) ? fcw : (fcw + 256);
        const int cs      = (L < 2) ? 128 : 0;
        const bool wh     = (L < 2);
        float rs[4] = {0.f, 0.f, 0.f, 0.f};
#pragma unroll
        for (int mt = 0; mt < 2; mt++)
#pragma unroll
            for (int j = 0; j < 16; j++)
#pragma unroll
                for (int r = 0; r < 4; r++) {
                    int row = wm * 32 + mt * 16 + (lane >> 2) + ((r >> 1) << 3);
                    int col = wn * 128 + j * 8 + ((lane & 3) << 1) + (r & 1);
                    float v = fmaxf(acc[mt][j][r] + __ldg(&bias[col]), 0.f);
                    if (wh && wn == 0) hsm[row * HS + col] = v;
                    if (col >= cs) rs[mt * 2 + (r >> 1)] += v * __ldg(&fa[col]);
                }
#pragma unroll
        for (int i = 0; i < 4; i++) {
            float v = rs[i];
            v += __shfl_xor_sync(0xffffffffu, v, 1);
            v += __shfl_xor_sync(0xffffffffu, v, 2);
            if ((lane & 3) == 0) {
                int row = wm * 32 + (i >> 1) * 16 + (lane >> 2) + ((i & 1) << 3);
                atomicAdd(&rowsum[row], v);
            }
        }
        __syncthreads();
    }

    // final: each 32-row group (= one batch element) reduces to one scalar
    if (tid < MT) {
        float v = rowsum[tid];
#pragma unroll
        for (int o = 16; o; o >>= 1) v += __shfl_xor_sync(0xffffffffu, v, o);
        if ((tid & 31) == 0) out[blockIdx.x * 4 + wid] = v + fcb[0];
    }
}

// ============================ launch =======================================
extern "C" void kernel_launch(void* const* d_in, const int* in_sizes, int n_in,
                              void* d_out, int out_size)
{
    const float* x   = (const float*)d_in[0];
    const float* W0  = (const float*)d_in[1];
    const float* b0  = (const float*)d_in[2];
    const float* W1  = (const float*)d_in[3];
    const float* b1  = (const float*)d_in[4];
    const float* W2  = (const float*)d_in[5];
    const float* b2  = (const float*)d_in[6];
    const float* fcw = (const float*)d_in[7];
    const float* fcb = (const float*)d_in[8];
    float* out = (float*)d_out;

    // weight shuffle/split (every launch; idempotent, graph-capturable)
    const int conv_smem = 64 * 257 * 4;
    cudaFuncSetAttribute(conv_kernel, cudaFuncAttributeMaxDynamicSharedMemorySize, conv_smem);
    conv_kernel<<<NCH0,  256, conv_smem>>>(W0, K0_REAL, 0);
    conv_kernel<<<NCH12, 256, conv_smem>>>(W1, K12, NCH0);
    conv_kernel<<<NCH12, 256, conv_smem>>>(W2, K12, NCH0 + NCH12);

    int B = in_sizes[0] / (F_DIM * 32);      // 1024
    int grid = (B * 32) / MT;                // 256

    cudaFuncSetAttribute(cin_mma, cudaFuncAttributeMaxDynamicSharedMemorySize, SM_TOT);
    cin_mma<<<grid, NT, SM_TOT>>>(x, b0, b1, b2, fcw, fcb, out);
}

// round 10
// speedup vs baseline: 1.9346x; 1.3422x over previous
#include <cuda_runtime.h>
#include <cuda_fp16.h>
#include <stdint.h>

// ============================ problem constants ============================
#define F_DIM   39
#define NT      256
#define MT      128              // rows (b,d) per CTA
#define NCH0    24               // layer0 k64 chunks (K padded 1521->1536)
#define NCH12   78               // layer1/2 chunks (4992 exact)
#define NCHT    (NCH0 + 2*NCH12) // 180
#define K0_REAL 1521
#define K12     4992

// weights: fp16 (hi only), fragment order:
// 16B unit idx = ((s*16 + gp)*32 + lane);  covers n-groups ng = 2gp, 2gp+1
//   n = ng*8 + lane/4,  k_in_chunk = s*16 + (lane%4)*2 (+1, +8, +9)
__device__ __align__(256) uint4 g_B[(size_t)NCHT * 2048];

// ============================ smem layout (bytes) ==========================
#define B_BUF  32768                     // per buffer, 2 buffers
#define SM_B   0
#define AS     36                        // A row stride in 4B words
#define SM_A   (2*B_BUF)                 // 65536 : A fp16 [128][AS words]
#define SM_X   (SM_A + 128*AS*4)         // 83968 : x fp32 [128][XS]
#define XS     41
#define SM_H   (SM_X + 128*XS*4)         // 104960: h fp32 [128][HS]
#define HS     132
#define SM_RS  (SM_H + 128*HS*4)         // 172544: rowsum[128]
#define SM_TOT (SM_RS + 512)             // 173056

// ============================ helpers ======================================
__device__ __forceinline__ uint32_t s2u(const void* p) {
    uint32_t a;
    asm("{ .reg .u64 t; cvta.to.shared.u64 t, %1; cvt.u32.u64 %0, t; }" : "=r"(a) : "l"(p));
    return a;
}
__device__ __forceinline__ void cp16(uint32_t s, const void* g) {
    asm volatile("cp.async.cg.shared.global [%0], [%1], 16;" :: "r"(s), "l"(g));
}
#define CP_COMMIT() asm volatile("cp.async.commit_group;")
#define CP_WAIT1()  asm volatile("cp.async.wait_group 1;" ::: "memory")

__device__ __forceinline__ void mma_f16(float* c, const uint32_t* a, uint32_t b0, uint32_t b1) {
    asm volatile("mma.sync.aligned.m16n8k16.row.col.f32.f16.f16.f32 "
        "{%0,%1,%2,%3}, {%4,%5,%6,%7}, {%8,%9}, {%0,%1,%2,%3};"
        : "+f"(c[0]), "+f"(c[1]), "+f"(c[2]), "+f"(c[3])
        : "r"(a[0]), "r"(a[1]), "r"(a[2]), "r"(a[3]), "r"(b0), "r"(b1));
}
__device__ __forceinline__ void lds128(uint32_t& r0, uint32_t& r1, uint32_t& r2, uint32_t& r3, uint32_t a) {
    asm volatile("ld.shared.v4.u32 {%0,%1,%2,%3}, [%4];"
        : "=r"(r0), "=r"(r1), "=r"(r2), "=r"(r3) : "r"(a));
}

// ================= weight shuffle kernel (fragment order) ==================
__global__ void conv_kernel(const float* __restrict__ W, int Kreal, int chunk0) {
    extern __shared__ float ws[];     // [64][257]
    const int lc = blockIdx.x, tid = threadIdx.x;
    for (int i = 0; i < 64; i++) {
        int k = lc * 64 + i;
        ws[i * 257 + tid] = (k < Kreal) ? W[(size_t)k * 256 + tid] : 0.f;
    }
    __syncthreads();
    const size_t base = (size_t)(chunk0 + lc) * 2048;
    for (int u = tid; u < 2048; u += 256) {
        int lane = u & 31, gp = (u >> 5) & 15, s = (u >> 9) & 3;
        int kb = s * 16 + (lane & 3) * 2;
        uint32_t wreg[4];
#pragma unroll
        for (int e = 0; e < 2; e++) {
            int n = (gp * 2 + e) * 8 + (lane >> 2);
            __half2 w0 = __floats2half2_rn(ws[kb * 257 + n],       ws[(kb + 1) * 257 + n]);
            __half2 w1 = __floats2half2_rn(ws[(kb + 8) * 257 + n], ws[(kb + 9) * 257 + n]);
            wreg[e * 2]     = *(uint32_t*)&w0;
            wreg[e * 2 + 1] = *(uint32_t*)&w1;
        }
        g_B[base + u] = make_uint4(wreg[0], wreg[1], wreg[2], wreg[3]);
    }
}

// =============== cooperative A generation: fp16 into SMEM ==================
// thread tid -> row m = tid/2, k-half = tid&1 (32 k each, 16 half2 words)
template<int HP, int HSTR>
__device__ __forceinline__ void gen_A(
    const float* __restrict__ xsm, const float* __restrict__ hb,
    uint32_t* __restrict__ Asm, int lch, int KR, int tid)
{
    const int m = tid >> 1;
    const int k0 = lch * 64 + (tid & 1) * 32;
    int f = k0 / HP, c = k0 - f * HP;
    const float* xrow = xsm + m * XS;
    const float* hrow = hb + m * HSTR;
    uint32_t* arow = Asm + m * AS + (tid & 1) * 16;
    float xa = xrow[f];
#pragma unroll
    for (int w = 0; w < 16; w++) {
        const int k = k0 + w * 2;
        float a0 = (k < KR) ? xa * hrow[c] : 0.f;
        if (++c == HP) { c = 0; xa = xrow[++f]; }
        float a1 = (k + 1 < KR) ? xa * hrow[c] : 0.f;
        if (++c == HP) { c = 0; xa = xrow[++f]; }
        __half2 p = __floats2half2_rn(a0, a1);
        arow[w] = *(uint32_t*)&p;
    }
}

// ===================== per-chunk MMA (one k64 chunk) =======================
// warp grid: wm in [0,4) -> 32-row M tile (2 mt x 16);  wn in [0,2) -> 128 cols
__device__ __forceinline__ void chunk_mma(
    const uint32_t* __restrict__ Asm, uint32_t bbuf, int lane, int wm, int wn,
    float (&acc)[2][16][4])
{
    const int rb = wm * 32 + (lane >> 2);
    const uint32_t blane = bbuf + (uint32_t)((wn * 8) * 32 + lane) * 16;
#pragma unroll
    for (int s = 0; s < 4; s++) {
        // A fragments: conflict-free lds32 from stride-36 A-smem
        uint32_t a[2][4];
#pragma unroll
        for (int mt = 0; mt < 2; mt++) {
            const uint32_t* ap = Asm + (rb + mt * 16) * AS + s * 8 + (lane & 3);
            a[mt][0] = ap[0];
            a[mt][1] = ap[8 * AS];
            a[mt][2] = ap[4];
            a[mt][3] = ap[8 * AS + 4];
        }
        const uint32_t rowa = blane + s * 8192;
#pragma unroll
        for (int jl = 0; jl < 8; jl++) {
            uint32_t b00, b01, b10, b11;
            lds128(b00, b01, b10, b11, rowa + jl * 512);
            mma_f16(acc[0][2 * jl],     a[0], b00, b01);
            mma_f16(acc[1][2 * jl],     a[1], b00, b01);
            mma_f16(acc[0][2 * jl + 1], a[0], b10, b11);
            mma_f16(acc[1][2 * jl + 1], a[1], b10, b11);
        }
    }
}

// ============================ main fused kernel ============================
__global__ void __launch_bounds__(NT, 1)
cin_mma(const float* __restrict__ x,
        const float* __restrict__ b0, const float* __restrict__ b1,
        const float* __restrict__ b2,
        const float* __restrict__ fcw, const float* __restrict__ fcb,
        float* __restrict__ out)
{
    extern __shared__ char sm[];
    const uint32_t smb = s2u(sm);
    uint32_t* Asm = (uint32_t*)(sm + SM_A);
    float* xsm = (float*)(sm + SM_X);
    float* hsm = (float*)(sm + SM_H);
    float* rowsum = (float*)(sm + SM_RS);

    const int tid = threadIdx.x, wid = tid >> 5, lane = tid & 31;
    const int wm = wid & 3, wn = wid >> 2;
    const int m0 = blockIdx.x * MT;

    if (tid < MT) rowsum[tid] = 0.f;

    // stage x tile: xsm[ml][f] = x[b, f, d];  m = m0+ml, b = m/32, d = m%32
    for (int i = tid; i < F_DIM * MT; i += NT) {
        int f = i >> 7, ml = i & 127, m = m0 + ml;
        xsm[ml * XS + f] = x[((size_t)(m >> 5) * F_DIM + f) * 32 + (m & 31)];
    }

    auto stage = [&](int gch, int q) {
        const uint4* src = g_B + (size_t)gch * 2048;
        const uint32_t dst = smb + SM_B + q * B_BUF;
        for (int i = tid; i < 2048; i += NT)
            cp16(dst + i * 16, src + i);
    };

    float acc[2][16][4];
    int gch = 0;
    stage(0, 0);
    CP_COMMIT();
    __syncthreads();    // x tile ready for gen_A

    for (int L = 0; L < 3; L++) {
        const int nch = (L == 0) ? NCH0 : NCH12;
        const int KR  = (L == 0) ? K0_REAL : K12;
#pragma unroll
        for (int mt = 0; mt < 2; mt++)
#pragma unroll
            for (int j = 0; j < 16; j++)
#pragma unroll
                for (int r = 0; r < 4; r++) acc[mt][j][r] = 0.f;

        for (int lch = 0; lch < nch; lch++, gch++) {
            const int q = gch & 1;
            if (gch + 1 < NCHT) stage(gch + 1, q ^ 1);
            CP_COMMIT();

            // cooperative A-gen for THIS chunk (overlaps in-flight cp.async)
            if (L == 0)
                gen_A<F_DIM, XS>(xsm, xsm, Asm, lch, KR, tid);
            else
                gen_A<128, HS>(xsm, hsm, Asm, lch, KR, tid);

            CP_WAIT1();
            __syncthreads();    // B staged + A visible

            chunk_mma(Asm, smb + SM_B + q * B_BUF, lane, wm, wn, acc);
            __syncthreads();    // all reads done before next gen/stage overwrite
        }

        // ---- layer epilogue: bias+relu, h feedback, fc_w partial dots ----
        const float* bias = (L == 0) ? b0 : (L == 1) ? b1 : b2;
        const float* fa   = (L == 0) ? (fcw - 128) : (L == 1) ? fcw : (fcw + 256);
        const int cs      = (L < 2) ? 128 : 0;
        const bool wh     = (L < 2);
        float rs[4] = {0.f, 0.f, 0.f, 0.f};
#pragma unroll
        for (int mt = 0; mt < 2; mt++)
#pragma unroll
            for (int j = 0; j < 16; j++)
#pragma unroll
                for (int r = 0; r < 4; r++) {
                    int row = wm * 32 + mt * 16 + (lane >> 2) + ((r >> 1) << 3);
                    int col = wn * 128 + j * 8 + ((lane & 3) << 1) + (r & 1);
                    float v = fmaxf(acc[mt][j][r] + __ldg(&bias[col]), 0.f);
                    if (wh && wn == 0) hsm[row * HS + col] = v;
                    if (col >= cs) rs[mt * 2 + (r >> 1)] += v * __ldg(&fa[col]);
                }
#pragma unroll
        for (int i = 0; i < 4; i++) {
            float v = rs[i];
            v += __shfl_xor_sync(0xffffffffu, v, 1);
            v += __shfl_xor_sync(0xffffffffu, v, 2);
            if ((lane & 3) == 0) {
                int row = wm * 32 + (i >> 1) * 16 + (lane >> 2) + ((i & 1) << 3);
                atomicAdd(&rowsum[row], v);
            }
        }
        __syncthreads();
    }

    // final: each 32-row group (= one batch element) reduces to one scalar
    if (tid < MT) {
        float v = rowsum[tid];
#pragma unroll
        for (int o = 16; o; o >>= 1) v += __shfl_xor_sync(0xffffffffu, v, o);
        if ((tid & 31) == 0) out[blockIdx.x * 4 + wid] = v + fcb[0];
    }
}

// ============================ launch =======================================
extern "C" void kernel_launch(void* const* d_in, const int* in_sizes, int n_in,
                              void* d_out, int out_size)
{
    const float* x   = (const float*)d_in[0];
    const float* W0  = (const float*)d_in[1];
    const float* b0  = (const float*)d_in[2];
    const float* W1  = (const float*)d_in[3];
    const float* b1  = (const float*)d_in[4];
    const float* W2  = (const float*)d_in[5];
    const float* b2  = (const float*)d_in[6];
    const float* fcw = (const float*)d_in[7];
    const float* fcb = (const float*)d_in[8];
    float* out = (float*)d_out;

    // weight shuffle/convert (every launch; idempotent, graph-capturable)
    const int conv_smem = 64 * 257 * 4;
    cudaFuncSetAttribute(conv_kernel, cudaFuncAttributeMaxDynamicSharedMemorySize, conv_smem);
    conv_kernel<<<NCH0,  256, conv_smem>>>(W0, K0_REAL, 0);
    conv_kernel<<<NCH12, 256, conv_smem>>>(W1, K12, NCH0);
    conv_kernel<<<NCH12, 256, conv_smem>>>(W2, K12, NCH0 + NCH12);

    int B = in_sizes[0] / (F_DIM * 32);      // 1024
    int grid = (B * 32) / MT;                // 256

    cudaFuncSetAttribute(cin_mma, cudaFuncAttributeMaxDynamicSharedMemorySize, SM_TOT);
    cin_mma<<<grid, NT, SM_TOT>>>(x, b0, b1, b2, fcw, fcb, out);
}

// round 11
// speedup vs baseline: 2.4119x; 1.2467x over previous
#include <cuda_runtime.h>
#include <cuda_fp16.h>
#include <stdint.h>

// ============================ problem constants ============================
#define F_DIM   39
#define NT      256
#define MT      128              // rows (b,d) per CTA
#define NCH0    24               // layer0 k64 chunks (K padded 1521->1536)
#define NCH12   78               // layer1/2 chunks (4992 exact)
#define NCHT    (NCH0 + 2*NCH12) // 180
#define K0_REAL 1521
#define K12     4992

// weights: fp16, fragment order:
// 16B unit idx = ((s*16 + gp)*32 + lane);  covers n-groups ng = 2gp, 2gp+1
//   n = ng*8 + lane/4,  k_in_chunk = s*16 + (lane%4)*2 (+1, +8, +9)
__device__ __align__(256) uint4 g_B[(size_t)NCHT * 2048];

// ============================ smem layout (bytes) ==========================
#define B_BUF  32768                     // per buffer, 2 buffers
#define SM_B   0
#define AS     36                        // A row stride in 4B words
#define SM_A   (2*B_BUF)                 // 65536 : A fp16 [128][AS words]
#define SM_X   (SM_A + 128*AS*4)         // 83968 : x fp32 [128][XS]
#define XS     41
#define SM_H   (SM_X + 128*XS*4)         // 104960: h fp32 [128][HS]
#define HS     132
#define SM_RS  (SM_H + 128*HS*4)         // 172544: rowsum[128]
#define SM_MB  (SM_RS + 512)             // 173056: 2 mbarriers (u64)
#define SM_TOT (SM_MB + 64)              // 173120

// ============================ helpers ======================================
__device__ __forceinline__ uint32_t s2u(const void* p) {
    uint32_t a;
    asm("{ .reg .u64 t; cvta.to.shared.u64 t, %1; cvt.u32.u64 %0, t; }" : "=r"(a) : "l"(p));
    return a;
}
#define MB_INIT(mb, c) asm volatile("mbarrier.init.shared.b64 [%0], %1;" :: "r"(mb), "r"(c) : "memory")

#define MB_WAIT(mb, par) do {                                                   \
    uint32_t _m = (mb), _p = (par), _d;                                         \
    asm volatile("{ .reg .pred p; mbarrier.try_wait.parity.shared.b64 p, [%1], %2; selp.b32 %0,1,0,p; }" \
        : "=r"(_d) : "r"(_m), "r"(_p) : "memory");                              \
    if (!_d) {                                                                  \
        asm volatile("{ .reg .pred P1; WL%=: mbarrier.try_wait.parity.shared.b64 P1, [%0], %1; @P1 bra.uni WD%=; bra.uni WL%=; WD%=: }" \
            :: "r"(_m), "r"(_p) : "memory");                                    \
    }                                                                           \
} while (0)

__device__ __forceinline__ void bulk_ld(uint32_t dst, const void* src, uint32_t bytes, uint32_t mb) {
    asm volatile("mbarrier.arrive.expect_tx.shared.b64 _, [%0], %1;" :: "r"(mb), "r"(bytes) : "memory");
    asm volatile("cp.async.bulk.shared::cluster.global.mbarrier::complete_tx::bytes [%0], [%1], %2, [%3];"
        :: "r"(dst), "l"(src), "r"(bytes), "r"(mb) : "memory");
}

__device__ __forceinline__ void mma_f16(float* c, const uint32_t* a, uint32_t b0, uint32_t b1) {
    asm volatile("mma.sync.aligned.m16n8k16.row.col.f32.f16.f16.f32 "
        "{%0,%1,%2,%3}, {%4,%5,%6,%7}, {%8,%9}, {%0,%1,%2,%3};"
        : "+f"(c[0]), "+f"(c[1]), "+f"(c[2]), "+f"(c[3])
        : "r"(a[0]), "r"(a[1]), "r"(a[2]), "r"(a[3]), "r"(b0), "r"(b1));
}
__device__ __forceinline__ void lds128(uint32_t& r0, uint32_t& r1, uint32_t& r2, uint32_t& r3, uint32_t a) {
    asm volatile("ld.shared.v4.u32 {%0,%1,%2,%3}, [%4];"
        : "=r"(r0), "=r"(r1), "=r"(r2), "=r"(r3) : "r"(a));
}

// ================= weight shuffle kernel (fragment order) ==================
__global__ void conv_kernel(const float* __restrict__ W, int Kreal, int chunk0) {
    extern __shared__ float ws[];     // [64][257]
    const int lc = blockIdx.x, tid = threadIdx.x;
    for (int i = 0; i < 64; i++) {
        int k = lc * 64 + i;
        ws[i * 257 + tid] = (k < Kreal) ? W[(size_t)k * 256 + tid] : 0.f;
    }
    __syncthreads();
    const size_t base = (size_t)(chunk0 + lc) * 2048;
    for (int u = tid; u < 2048; u += 256) {
        int lane = u & 31, gp = (u >> 5) & 15, s = (u >> 9) & 3;
        int kb = s * 16 + (lane & 3) * 2;
        uint32_t wreg[4];
#pragma unroll
        for (int e = 0; e < 2; e++) {
            int n = (gp * 2 + e) * 8 + (lane >> 2);
            __half2 w0 = __floats2half2_rn(ws[kb * 257 + n],       ws[(kb + 1) * 257 + n]);
            __half2 w1 = __floats2half2_rn(ws[(kb + 8) * 257 + n], ws[(kb + 9) * 257 + n]);
            wreg[e * 2]     = *(uint32_t*)&w0;
            wreg[e * 2 + 1] = *(uint32_t*)&w1;
        }
        g_B[base + u] = make_uint4(wreg[0], wreg[1], wreg[2], wreg[3]);
    }
}

// =============== cooperative A generation: fp16 into SMEM ==================
// thread tid -> row m = tid/2, k-half = tid&1 (32 k each, 16 half2 words)

// generic (layer 0, HP=39): f/c bookkeeping + tail masking
__device__ __forceinline__ void gen_A0(
    const float* __restrict__ xsm, uint32_t* __restrict__ Asm,
    int lch, int tid)
{
    const int m = tid >> 1;
    const int k0 = lch * 64 + (tid & 1) * 32;
    int f = k0 / F_DIM, c = k0 - f * F_DIM;
    const float* xrow = xsm + m * XS;
    uint32_t* arow = Asm + m * AS + (tid & 1) * 16;
    float xa = xrow[f];
#pragma unroll
    for (int w = 0; w < 16; w++) {
        const int k = k0 + w * 2;
        float a0 = (k < K0_REAL) ? xa * xrow[c] : 0.f;
        if (++c == F_DIM) { c = 0; xa = xrow[++f]; }
        float a1 = (k + 1 < K0_REAL) ? xa * xrow[c] : 0.f;
        if (++c == F_DIM) { c = 0; xa = xrow[++f]; }
        __half2 p = __floats2half2_rn(a0, a1);
        arow[w] = *(uint32_t*)&p;
    }
}

// aligned (layers 1/2, HP=128): f constant, c in-row, float2 h loads
__device__ __forceinline__ void gen_A12(
    const float* __restrict__ xsm, const float* __restrict__ hsm,
    uint32_t* __restrict__ Asm, int lch, int tid)
{
    const int m = tid >> 1;
    const int k0 = lch * 64 + (tid & 1) * 32;
    const int f = k0 >> 7, c0 = k0 & 127;
    const float xa = xsm[m * XS + f];
    const float2* hrow = (const float2*)(hsm + m * HS + c0);
    uint32_t* arow = Asm + m * AS + (tid & 1) * 16;
#pragma unroll
    for (int w = 0; w < 16; w++) {
        float2 hh = hrow[w];
        __half2 p = __floats2half2_rn(xa * hh.x, xa * hh.y);
        arow[w] = *(uint32_t*)&p;
    }
}

// ===================== per-chunk MMA (one k64 chunk) =======================
// warp grid: wm in [0,4) -> 32-row M tile (2 mt x 16);  wn in [0,2) -> 128 cols
__device__ __forceinline__ void chunk_mma(
    const uint32_t* __restrict__ Asm, uint32_t bbuf, int lane, int wm, int wn,
    float (&acc)[2][16][4])
{
    const int rb = wm * 32 + (lane >> 2);
    const uint32_t blane = bbuf + (uint32_t)((wn * 8) * 32 + lane) * 16;
#pragma unroll
    for (int s = 0; s < 4; s++) {
        // A fragments: conflict-free lds32 from stride-36 A-smem
        uint32_t a[2][4];
#pragma unroll
        for (int mt = 0; mt < 2; mt++) {
            const uint32_t* ap = Asm + (rb + mt * 16) * AS + s * 8 + (lane & 3);
            a[mt][0] = ap[0];
            a[mt][1] = ap[8 * AS];
            a[mt][2] = ap[4];
            a[mt][3] = ap[8 * AS + 4];
        }
        const uint32_t rowa = blane + s * 8192;
#pragma unroll
        for (int jl = 0; jl < 8; jl++) {
            uint32_t b00, b01, b10, b11;
            lds128(b00, b01, b10, b11, rowa + jl * 512);
            mma_f16(acc[0][2 * jl],     a[0], b00, b01);
            mma_f16(acc[1][2 * jl],     a[1], b00, b01);
            mma_f16(acc[0][2 * jl + 1], a[0], b10, b11);
            mma_f16(acc[1][2 * jl + 1], a[1], b10, b11);
        }
    }
}

// ============================ main fused kernel ============================
__global__ void __launch_bounds__(NT, 1)
cin_mma(const float* __restrict__ x,
        const float* __restrict__ b0, const float* __restrict__ b1,
        const float* __restrict__ b2,
        const float* __restrict__ fcw, const float* __restrict__ fcb,
        float* __restrict__ out)
{
    extern __shared__ char sm[];
    const uint32_t smb = s2u(sm);
    uint32_t* Asm = (uint32_t*)(sm + SM_A);
    float* xsm = (float*)(sm + SM_X);
    float* hsm = (float*)(sm + SM_H);
    float* rowsum = (float*)(sm + SM_RS);

    const int tid = threadIdx.x, wid = tid >> 5, lane = tid & 31;
    const int wm = wid & 3, wn = wid >> 2;
    const int m0 = blockIdx.x * MT;

    if (tid < MT) rowsum[tid] = 0.f;
    if (tid == 0) { MB_INIT(smb + SM_MB, 1); MB_INIT(smb + SM_MB + 8, 1); }

    // stage x tile: xsm[ml][f] = x[b, f, d];  m = m0+ml, b = m/32, d = m%32
    for (int i = tid; i < F_DIM * MT; i += NT) {
        int f = i >> 7, ml = i & 127, m = m0 + ml;
        xsm[ml * XS + f] = x[((size_t)(m >> 5) * F_DIM + f) * 32 + (m & 31)];
    }
    __syncthreads();    // x ready, mbarriers visible

    // bulk-stage B chunk gch into buffer q (single instruction, DMA-fed)
    auto stage = [&](int gch, int q) {
        if (tid == 0)
            bulk_ld(smb + SM_B + q * B_BUF, g_B + (size_t)gch * 2048, B_BUF,
                    smb + SM_MB + q * 8);
    };

    float acc[2][16][4];
    uint32_t ph[2] = {0, 0};
    int gch = 0;
    stage(0, 0);
    stage(1, 1);

    for (int L = 0; L < 3; L++) {
        const int nch = (L == 0) ? NCH0 : NCH12;
#pragma unroll
        for (int mt = 0; mt < 2; mt++)
#pragma unroll
            for (int j = 0; j < 16; j++)
#pragma unroll
                for (int r = 0; r < 4; r++) acc[mt][j][r] = 0.f;

        for (int lch = 0; lch < nch; lch++, gch++) {
            const int q = gch & 1;

            // cooperative A-gen for THIS chunk (overlaps in-flight bulk copy)
            if (L == 0) gen_A0(xsm, Asm, lch, tid);
            else        gen_A12(xsm, hsm, Asm, lch, tid);

            MB_WAIT(smb + SM_MB + q * 8, ph[q]);    // B chunk resident
            ph[q] ^= 1;
            __syncthreads();                         // A visible to all warps

            chunk_mma(Asm, smb + SM_B + q * B_BUF, lane, wm, wn, acc);
            __syncthreads();                         // B reads done before refill

            if (gch + 2 < NCHT) stage(gch + 2, q);
        }

        // ---- layer epilogue: bias+relu, h feedback, fc_w partial dots ----
        const float* bias = (L == 0) ? b0 : (L == 1) ? b1 : b2;
        const float* fa   = (L == 0) ? (fcw - 128) : (L == 1) ? fcw : (fcw + 256);
        const int cs      = (L < 2) ? 128 : 0;
        const bool wh     = (L < 2);
        float rs[4] = {0.f, 0.f, 0.f, 0.f};
#pragma unroll
        for (int mt = 0; mt < 2; mt++)
#pragma unroll
            for (int j = 0; j < 16; j++)
#pragma unroll
                for (int r = 0; r < 4; r++) {
                    int row = wm * 32 + mt * 16 + (lane >> 2) + ((r >> 1) << 3);
                    int col = wn * 128 + j * 8 + ((lane & 3) << 1) + (r & 1);
                    float v = fmaxf(acc[mt][j][r] + __ldg(&bias[col]), 0.f);
                    if (wh && wn == 0) hsm[row * HS + col] = v;
                    if (col >= cs) rs[mt * 2 + (r >> 1)] += v * __ldg(&fa[col]);
                }
#pragma unroll
        for (int i = 0; i < 4; i++) {
            float v = rs[i];
            v += __shfl_xor_sync(0xffffffffu, v, 1);
            v += __shfl_xor_sync(0xffffffffu, v, 2);
            if ((lane & 3) == 0) {
                int row = wm * 32 + (i >> 1) * 16 + (lane >> 2) + ((i & 1) << 3);
                atomicAdd(&rowsum[row], v);
            }
        }
        __syncthreads();
    }

    // final: each 32-row group (= one batch element) reduces to one scalar
    if (tid < MT) {
        float v = rowsum[tid];
#pragma unroll
        for (int o = 16; o; o >>= 1) v += __shfl_xor_sync(0xffffffffu, v, o);
        if ((tid & 31) == 0) out[blockIdx.x * 4 + wid] = v + fcb[0];
    }
}

// ============================ launch =======================================
extern "C" void kernel_launch(void* const* d_in, const int* in_sizes, int n_in,
                              void* d_out, int out_size)
{
    const float* x   = (const float*)d_in[0];
    const float* W0  = (const float*)d_in[1];
    const float* b0  = (const float*)d_in[2];
    const float* W1  = (const float*)d_in[3];
    const float* b1  = (const float*)d_in[4];
    const float* W2  = (const float*)d_in[5];
    const float* b2  = (const float*)d_in[6];
    const float* fcw = (const float*)d_in[7];
    const float* fcb = (const float*)d_in[8];
    float* out = (float*)d_out;

    // weight shuffle/convert (every launch; idempotent, graph-capturable)
    const int conv_smem = 64 * 257 * 4;
    cudaFuncSetAttribute(conv_kernel, cudaFuncAttributeMaxDynamicSharedMemorySize, conv_smem);
    conv_kernel<<<NCH0,  256, conv_smem>>>(W0, K0_REAL, 0);
    conv_kernel<<<NCH12, 256, conv_smem>>>(W1, K12, NCH0);
    conv_kernel<<<NCH12, 256, conv_smem>>>(W2, K12, NCH0 + NCH12);

    int B = in_sizes[0] / (F_DIM * 32);      // 1024
    int grid = (B * 32) / MT;                // 256

    cudaFuncSetAttribute(cin_mma, cudaFuncAttributeMaxDynamicSharedMemorySize, SM_TOT);
    cin_mma<<<grid, NT, SM_TOT>>>(x, b0, b1, b2, fcw, fcb, out);
}

// round 12
// speedup vs baseline: 2.6640x; 1.1045x over previous
#include <cuda_runtime.h>
#include <cuda_fp16.h>
#include <stdint.h>

// ============================ problem constants ============================
#define F_DIM   39
#define NT      256
#define MT      128              // rows (b,d) per CTA
#define NCH0    24               // layer0 k64 chunks (K padded 1521->1536)
#define NCH12   78               // layer1/2 chunks (4992 exact)
#define NCHT    (NCH0 + 2*NCH12) // 180
#define K0_REAL 1521
#define K12     4992

// weights: fp16, fragment order:
// 16B unit idx = ((s*16 + gp)*32 + lane);  covers n-groups ng = 2gp, 2gp+1
//   n = ng*8 + lane/4,  k_in_chunk = s*16 + (lane%4)*2 (+1, +8, +9)
__device__ __align__(256) uint4 g_B[(size_t)NCHT * 2048];

// ============================ smem layout (bytes) ==========================
#define B_BUF  32768                     // per buffer, 3 buffers
#define SM_B   0
#define AS     36                        // A row stride in 4B words
#define A_BUF  (128*AS*4)                // 18432, 2 buffers
#define SM_A   (3*B_BUF)                 // 98304
#define SM_X   (SM_A + 2*A_BUF)          // 135168 : x fp32 [128][XS]
#define XS     41
#define SM_H   (SM_X + 128*XS*4)         // 156160 : h fp32 [128][HS]
#define HS     132
#define SM_RS  (SM_H + 128*HS*4)         // 223744 : rowsum[128]
#define SM_MB  (SM_RS + 512)             // 224256 : 3 mbarriers
#define SM_TOT (SM_MB + 64)              // 224320

// ============================ helpers ======================================
__device__ __forceinline__ uint32_t s2u(const void* p) {
    uint32_t a;
    asm("{ .reg .u64 t; cvta.to.shared.u64 t, %1; cvt.u32.u64 %0, t; }" : "=r"(a) : "l"(p));
    return a;
}
#define MB_INIT(mb, c) asm volatile("mbarrier.init.shared.b64 [%0], %1;" :: "r"(mb), "r"(c) : "memory")

#define MB_WAIT(mb, par) do {                                                   \
    uint32_t _m = (mb), _p = (par), _d;                                         \
    asm volatile("{ .reg .pred p; mbarrier.try_wait.parity.shared.b64 p, [%1], %2; selp.b32 %0,1,0,p; }" \
        : "=r"(_d) : "r"(_m), "r"(_p) : "memory");                              \
    if (!_d) {                                                                  \
        asm volatile("{ .reg .pred P1; WL%=: mbarrier.try_wait.parity.shared.b64 P1, [%0], %1; @P1 bra.uni WD%=; bra.uni WL%=; WD%=: }" \
            :: "r"(_m), "r"(_p) : "memory");                                    \
    }                                                                           \
} while (0)

__device__ __forceinline__ void bulk_ld(uint32_t dst, const void* src, uint32_t bytes, uint32_t mb) {
    asm volatile("mbarrier.arrive.expect_tx.shared.b64 _, [%0], %1;" :: "r"(mb), "r"(bytes) : "memory");
    asm volatile("cp.async.bulk.shared::cluster.global.mbarrier::complete_tx::bytes [%0], [%1], %2, [%3];"
        :: "r"(dst), "l"(src), "r"(bytes), "r"(mb) : "memory");
}

__device__ __forceinline__ void mma_f16(float* c, const uint32_t* a, uint32_t b0, uint32_t b1) {
    asm volatile("mma.sync.aligned.m16n8k16.row.col.f32.f16.f16.f32 "
        "{%0,%1,%2,%3}, {%4,%5,%6,%7}, {%8,%9}, {%0,%1,%2,%3};"
        : "+f"(c[0]), "+f"(c[1]), "+f"(c[2]), "+f"(c[3])
        : "r"(a[0]), "r"(a[1]), "r"(a[2]), "r"(a[3]), "r"(b0), "r"(b1));
}
__device__ __forceinline__ void lds128(uint32_t& r0, uint32_t& r1, uint32_t& r2, uint32_t& r3, uint32_t a) {
    asm volatile("ld.shared.v4.u32 {%0,%1,%2,%3}, [%4];"
        : "=r"(r0), "=r"(r1), "=r"(r2), "=r"(r3) : "r"(a));
}

// ================= weight shuffle kernel (fragment order) ==================
__global__ void conv_kernel(const float* __restrict__ W, int Kreal, int chunk0) {
    extern __shared__ float ws[];     // [64][257]
    const int lc = blockIdx.x, tid = threadIdx.x;
    for (int i = 0; i < 64; i++) {
        int k = lc * 64 + i;
        ws[i * 257 + tid] = (k < Kreal) ? W[(size_t)k * 256 + tid] : 0.f;
    }
    __syncthreads();
    const size_t base = (size_t)(chunk0 + lc) * 2048;
    for (int u = tid; u < 2048; u += 256) {
        int lane = u & 31, gp = (u >> 5) & 15, s = (u >> 9) & 3;
        int kb = s * 16 + (lane & 3) * 2;
        uint32_t wreg[4];
#pragma unroll
        for (int e = 0; e < 2; e++) {
            int n = (gp * 2 + e) * 8 + (lane >> 2);
            __half2 w0 = __floats2half2_rn(ws[kb * 257 + n],       ws[(kb + 1) * 257 + n]);
            __half2 w1 = __floats2half2_rn(ws[(kb + 8) * 257 + n], ws[(kb + 9) * 257 + n]);
            wreg[e * 2]     = *(uint32_t*)&w0;
            wreg[e * 2 + 1] = *(uint32_t*)&w1;
        }
        g_B[base + u] = make_uint4(wreg[0], wreg[1], wreg[2], wreg[3]);
    }
}

// =============== cooperative A generation: fp16 into SMEM ==================
// thread tid -> row m = tid/2, k-half = tid&1 (32 k each, 16 half2 words)
__device__ __forceinline__ void gen_A0(
    const float* __restrict__ xsm, uint32_t* __restrict__ Asm,
    int lch, int tid)
{
    const int m = tid >> 1;
    const int k0 = lch * 64 + (tid & 1) * 32;
    int f = k0 / F_DIM, c = k0 - f * F_DIM;
    const float* xrow = xsm + m * XS;
    uint32_t* arow = Asm + m * AS + (tid & 1) * 16;
    float xa = xrow[f];
#pragma unroll
    for (int w = 0; w < 16; w++) {
        const int k = k0 + w * 2;
        float a0 = (k < K0_REAL) ? xa * xrow[c] : 0.f;
        if (++c == F_DIM) { c = 0; xa = xrow[++f]; }
        float a1 = (k + 1 < K0_REAL) ? xa * xrow[c] : 0.f;
        if (++c == F_DIM) { c = 0; xa = xrow[++f]; }
        __half2 p = __floats2half2_rn(a0, a1);
        arow[w] = *(uint32_t*)&p;
    }
}

__device__ __forceinline__ void gen_A12(
    const float* __restrict__ xsm, const float* __restrict__ hsm,
    uint32_t* __restrict__ Asm, int lch, int tid)
{
    const int m = tid >> 1;
    const int k0 = lch * 64 + (tid & 1) * 32;
    const int f = k0 >> 7, c0 = k0 & 127;
    const float xa = xsm[m * XS + f];
    const float2* hrow = (const float2*)(hsm + m * HS + c0);
    uint32_t* arow = Asm + m * AS + (tid & 1) * 16;
#pragma unroll
    for (int w = 0; w < 16; w++) {
        float2 hh = hrow[w];
        __half2 p = __floats2half2_rn(xa * hh.x, xa * hh.y);
        arow[w] = *(uint32_t*)&p;
    }
}

// ===================== per-chunk MMA (one k64 chunk) =======================
// warp grid 2M x 4N: wm in [0,2) -> 64-row tile (4 mt x 16);
//                    wn in [0,4) -> 64-col tile (8 n8-tiles)
__device__ __forceinline__ void chunk_mma(
    const uint32_t* __restrict__ Asm, uint32_t bbuf, int lane, int wm, int wn,
    float (&acc)[4][8][4])
{
    const int rb = wm * 64 + (lane >> 2);
    const uint32_t blane = bbuf + (uint32_t)(wn * 2048 + lane * 16);
#pragma unroll
    for (int s = 0; s < 4; s++) {
        // B fragments: 4 lds128 (each = 2 n-tiles)
        uint32_t bfr[4][4];
#pragma unroll
        for (int g = 0; g < 4; g++)
            lds128(bfr[g][0], bfr[g][1], bfr[g][2], bfr[g][3],
                   blane + s * 8192 + g * 512);
        // A fragments: conflict-free lds32 (stride-36 rows)
        uint32_t a[4][4];
#pragma unroll
        for (int mt = 0; mt < 4; mt++) {
            const uint32_t* ap = Asm + (rb + mt * 16) * AS + s * 8 + (lane & 3);
            a[mt][0] = ap[0];
            a[mt][1] = ap[8 * AS];
            a[mt][2] = ap[4];
            a[mt][3] = ap[8 * AS + 4];
        }
        // 32 MMAs: 4 independent mt per B-pair
#pragma unroll
        for (int g = 0; g < 4; g++)
#pragma unroll
            for (int e = 0; e < 2; e++)
#pragma unroll
                for (int mt = 0; mt < 4; mt++)
                    mma_f16(acc[mt][g * 2 + e], a[mt], bfr[g][e * 2], bfr[g][e * 2 + 1]);
    }
}

// ============================ main fused kernel ============================
__global__ void __launch_bounds__(NT, 1)
cin_mma(const float* __restrict__ x,
        const float* __restrict__ b0, const float* __restrict__ b1,
        const float* __restrict__ b2,
        const float* __restrict__ fcw, const float* __restrict__ fcb,
        float* __restrict__ out)
{
    extern __shared__ char sm[];
    const uint32_t smb = s2u(sm);
    float* xsm = (float*)(sm + SM_X);
    float* hsm = (float*)(sm + SM_H);
    float* rowsum = (float*)(sm + SM_RS);

    const int tid = threadIdx.x, wid = tid >> 5, lane = tid & 31;
    const int wm = wid & 1, wn = wid >> 1;
    const int m0 = blockIdx.x * MT;

    if (tid < MT) rowsum[tid] = 0.f;
    if (tid == 0) {
        MB_INIT(smb + SM_MB, 1); MB_INIT(smb + SM_MB + 8, 1); MB_INIT(smb + SM_MB + 16, 1);
    }

    // stage x tile: xsm[ml][f] = x[b, f, d];  m = m0+ml, b = m/32, d = m%32
    for (int i = tid; i < F_DIM * MT; i += NT) {
        int f = i >> 7, ml = i & 127, m = m0 + ml;
        xsm[ml * XS + f] = x[((size_t)(m >> 5) * F_DIM + f) * 32 + (m & 31)];
    }
    __syncthreads();    // x ready, mbarriers visible

    auto stage = [&](int gch) {
        if (tid == 0)
            bulk_ld(smb + SM_B + (gch % 3) * B_BUF, g_B + (size_t)gch * 2048, B_BUF,
                    smb + SM_MB + (gch % 3) * 8);
    };

    float acc[4][8][4];
    uint32_t ph[3] = {0, 0, 0};
    int gch = 0;
    stage(0);
    stage(1);

    for (int L = 0; L < 3; L++) {
        const int nch = (L == 0) ? NCH0 : NCH12;
#pragma unroll
        for (int mt = 0; mt < 4; mt++)
#pragma unroll
            for (int j = 0; j < 8; j++)
#pragma unroll
                for (int r = 0; r < 4; r++) acc[mt][j][r] = 0.f;

        for (int lch = 0; lch < nch; lch++, gch++) {
            const int q = gch % 3;
            uint32_t* Asm = (uint32_t*)(sm + SM_A + (gch & 1) * A_BUF);

            // A-gen for THIS chunk (A-buffer parity keeps it clear of the
            // previous chunk's still-running MMAs)
            if (L == 0) gen_A0(xsm, Asm, lch, tid);
            else        gen_A12(xsm, hsm, Asm, lch, tid);

            MB_WAIT(smb + SM_MB + q * 8, ph[q]);    // B chunk resident
            ph[q] ^= 1;
            __syncthreads();    // A visible; ALL warps done with chunk gch-1
                                // => buffer (gch+2)%3 (last used by gch-1) is free
            if (gch + 2 < NCHT) stage(gch + 2);

            chunk_mma(Asm, smb + SM_B + q * B_BUF, lane, wm, wn, acc);
            // no trailing barrier: warps drift, next chunk's sync re-converges
        }

        // ---- layer epilogue: bias+relu, h feedback, fc_w partial dots ----
        // (no barrier needed first: acc is register-local; hsm writes race only
        //  with other epilogue warps' disjoint rows)
        const float* bias = (L == 0) ? b0 : (L == 1) ? b1 : b2;
        const float* fa   = (L == 0) ? (fcw - 128) : (L == 1) ? fcw : (fcw + 256);
        const int cs      = (L < 2) ? 128 : 0;
        const bool wh     = (L < 2);
        float rs[8] = {0.f, 0.f, 0.f, 0.f, 0.f, 0.f, 0.f, 0.f};
#pragma unroll
        for (int mt = 0; mt < 4; mt++)
#pragma unroll
            for (int j = 0; j < 8; j++)
#pragma unroll
                for (int r = 0; r < 4; r++) {
                    int row = wm * 64 + mt * 16 + (lane >> 2) + ((r >> 1) << 3);
                    int col = wn * 64 + j * 8 + ((lane & 3) << 1) + (r & 1);
                    float v = fmaxf(acc[mt][j][r] + __ldg(&bias[col]), 0.f);
                    if (wh && col < 128) hsm[row * HS + col] = v;
                    if (col >= cs) rs[mt * 2 + (r >> 1)] += v * __ldg(&fa[col]);
                }
#pragma unroll
        for (int i = 0; i < 8; i++) {
            float v = rs[i];
            v += __shfl_xor_sync(0xffffffffu, v, 1);
            v += __shfl_xor_sync(0xffffffffu, v, 2);
            if ((lane & 3) == 0) {
                int row = wm * 64 + (i >> 1) * 16 + (lane >> 2) + ((i & 1) << 3);
                atomicAdd(&rowsum[row], v);
            }
        }
        __syncthreads();    // h + rowsum complete before next layer reads
    }

    // final: each 32-row group (= one batch element) reduces to one scalar
    if (tid < MT) {
        float v = rowsum[tid];
#pragma unroll
        for (int o = 16; o; o >>= 1) v += __shfl_xor_sync(0xffffffffu, v, o);
        if ((tid & 31) == 0) out[blockIdx.x * 4 + wid] = v + fcb[0];
    }
}

// ============================ launch =======================================
extern "C" void kernel_launch(void* const* d_in, const int* in_sizes, int n_in,
                              void* d_out, int out_size)
{
    const float* x   = (const float*)d_in[0];
    const float* W0  = (const float*)d_in[1];
    const float* b0  = (const float*)d_in[2];
    const float* W1  = (const float*)d_in[3];
    const float* b1  = (const float*)d_in[4];
    const float* W2  = (const float*)d_in[5];
    const float* b2  = (const float*)d_in[6];
    const float* fcw = (const float*)d_in[7];
    const float* fcb = (const float*)d_in[8];
    float* out = (float*)d_out;

    // weight shuffle/convert (every launch; idempotent, graph-capturable)
    const int conv_smem = 64 * 257 * 4;
    cudaFuncSetAttribute(conv_kernel, cudaFuncAttributeMaxDynamicSharedMemorySize, conv_smem);
    conv_kernel<<<NCH0,  256, conv_smem>>>(W0, K0_REAL, 0);
    conv_kernel<<<NCH12, 256, conv_smem>>>(W1, K12, NCH0);
    conv_kernel<<<NCH12, 256, conv_smem>>>(W2, K12, NCH0 + NCH12);

    int B = in_sizes[0] / (F_DIM * 32);      // 1024
    int grid = (B * 32) / MT;                // 256

    cudaFuncSetAttribute(cin_mma, cudaFuncAttributeMaxDynamicSharedMemorySize, SM_TOT);
    cin_mma<<<grid, NT, SM_TOT>>>(x, b0, b1, b2, fcw, fcb, out);
}

// round 13
// speedup vs baseline: 2.6716x; 1.0028x over previous
#include <cuda_runtime.h>
#include <cuda_fp16.h>
#include <stdint.h>

// ============================ problem constants ============================
#define F_DIM   39
#define NT      256
#define MT      128              // rows (b,d) per CTA
#define NCH0    24               // layer0 k64 chunks (K padded 1521->1536)
#define NCH12   78               // layer1/2 chunks (4992 exact)
#define NCHT    (NCH0 + 2*NCH12) // 180
#define K0_REAL 1521
#define K12     4992

// weights: fp16, fragment order:
// 16B unit idx = ((s*16 + gp)*32 + lane);  covers n-groups ng = 2gp, 2gp+1
//   n = ng*8 + lane/4,  k_in_chunk = s*16 + (lane%4)*2 (+1, +8, +9)
__device__ __align__(256) uint4 g_B[(size_t)NCHT * 2048];

// ============================ smem layout (bytes) ==========================
#define B_BUF  32768                     // per buffer, 3 buffers
#define SM_B   0
#define AS     36                        // A row stride in 4B words (144B)
#define A_BUF  (128*AS*4)                // 18432, 2 buffers
#define SM_A   (3*B_BUF)                 // 98304
#define SM_X   (SM_A + 2*A_BUF)          // 135168 : x fp32 [128][XS]
#define XS     41
#define SM_H   (SM_X + 128*XS*4)         // 156160 : h fp32 [128][HS]
#define HS     132
#define SM_RS  (SM_H + 128*HS*4)         // 223744 : rowsum[128]
#define SM_MB  (SM_RS + 512)             // 224256 : 3 mbarriers
#define SM_TOT (SM_MB + 64)              // 224320

// ============================ helpers ======================================
__device__ __forceinline__ uint32_t s2u(const void* p) {
    uint32_t a;
    asm("{ .reg .u64 t; cvta.to.shared.u64 t, %1; cvt.u32.u64 %0, t; }" : "=r"(a) : "l"(p));
    return a;
}
#define MB_INIT(mb, c) asm volatile("mbarrier.init.shared.b64 [%0], %1;" :: "r"(mb), "r"(c) : "memory")

#define MB_WAIT(mb, par) do {                                                   \
    uint32_t _m = (mb), _p = (par), _d;                                         \
    asm volatile("{ .reg .pred p; mbarrier.try_wait.parity.shared.b64 p, [%1], %2; selp.b32 %0,1,0,p; }" \
        : "=r"(_d) : "r"(_m), "r"(_p) : "memory");                              \
    if (!_d) {                                                                  \
        asm volatile("{ .reg .pred P1; WL%=: mbarrier.try_wait.parity.shared.b64 P1, [%0], %1; @P1 bra.uni WD%=; bra.uni WL%=; WD%=: }" \
            :: "r"(_m), "r"(_p) : "memory");                                    \
    }                                                                           \
} while (0)

__device__ __forceinline__ void bulk_ld(uint32_t dst, const void* src, uint32_t bytes, uint32_t mb) {
    asm volatile("mbarrier.arrive.expect_tx.shared.b64 _, [%0], %1;" :: "r"(mb), "r"(bytes) : "memory");
    asm volatile("cp.async.bulk.shared::cluster.global.mbarrier::complete_tx::bytes [%0], [%1], %2, [%3];"
        :: "r"(dst), "l"(src), "r"(bytes), "r"(mb) : "memory");
}

__device__ __forceinline__ void mma_f16(float* c, const uint32_t* a, uint32_t b0, uint32_t b1) {
    asm volatile("mma.sync.aligned.m16n8k16.row.col.f32.f16.f16.f32 "
        "{%0,%1,%2,%3}, {%4,%5,%6,%7}, {%8,%9}, {%0,%1,%2,%3};"
        : "+f"(c[0]), "+f"(c[1]), "+f"(c[2]), "+f"(c[3])
        : "r"(a[0]), "r"(a[1]), "r"(a[2]), "r"(a[3]), "r"(b0), "r"(b1));
}
__device__ __forceinline__ void lds128(uint32_t& r0, uint32_t& r1, uint32_t& r2, uint32_t& r3, uint32_t a) {
    asm volatile("ld.shared.v4.u32 {%0,%1,%2,%3}, [%4];"
        : "=r"(r0), "=r"(r1), "=r"(r2), "=r"(r3) : "r"(a));
}
__device__ __forceinline__ void ldmx4(uint32_t* r, uint32_t a) {
    asm volatile("ldmatrix.sync.aligned.m8n8.x4.shared.b16 {%0,%1,%2,%3}, [%4];"
        : "=r"(r[0]), "=r"(r[1]), "=r"(r[2]), "=r"(r[3]) : "r"(a));
}

// ================= weight shuffle kernel (fragment order) ==================
__global__ void conv_kernel(const float* __restrict__ W, int Kreal, int chunk0) {
    extern __shared__ float ws[];     // [64][257]
    const int lc = blockIdx.x, tid = threadIdx.x;
    for (int i = 0; i < 64; i++) {
        int k = lc * 64 + i;
        ws[i * 257 + tid] = (k < Kreal) ? W[(size_t)k * 256 + tid] : 0.f;
    }
    __syncthreads();
    const size_t base = (size_t)(chunk0 + lc) * 2048;
    for (int u = tid; u < 2048; u += 256) {
        int lane = u & 31, gp = (u >> 5) & 15, s = (u >> 9) & 3;
        int kb = s * 16 + (lane & 3) * 2;
        uint32_t wreg[4];
#pragma unroll
        for (int e = 0; e < 2; e++) {
            int n = (gp * 2 + e) * 8 + (lane >> 2);
            __half2 w0 = __floats2half2_rn(ws[kb * 257 + n],       ws[(kb + 1) * 257 + n]);
            __half2 w1 = __floats2half2_rn(ws[(kb + 8) * 257 + n], ws[(kb + 9) * 257 + n]);
            wreg[e * 2]     = *(uint32_t*)&w0;
            wreg[e * 2 + 1] = *(uint32_t*)&w1;
        }
        g_B[base + u] = make_uint4(wreg[0], wreg[1], wreg[2], wreg[3]);
    }
}

// =============== cooperative A generation: fp16 into SMEM ==================
// thread tid -> row m = tid/2, k-half = tid&1 (32 k each, 16 half2 words)
__device__ __forceinline__ void gen_A0(
    const float* __restrict__ xsm, uint32_t* __restrict__ Asm,
    int lch, int tid)
{
    const int m = tid >> 1;
    const int k0 = lch * 64 + (tid & 1) * 32;
    int f = k0 / F_DIM, c = k0 - f * F_DIM;
    const float* xrow = xsm + m * XS;
    uint32_t* arow = Asm + m * AS + (tid & 1) * 16;
    float xa = xrow[f];
#pragma unroll
    for (int w = 0; w < 16; w++) {
        const int k = k0 + w * 2;
        float a0 = (k < K0_REAL) ? xa * xrow[c] : 0.f;
        if (++c == F_DIM) { c = 0; xa = xrow[++f]; }
        float a1 = (k + 1 < K0_REAL) ? xa * xrow[c] : 0.f;
        if (++c == F_DIM) { c = 0; xa = xrow[++f]; }
        __half2 p = __floats2half2_rn(a0, a1);
        arow[w] = *(uint32_t*)&p;
    }
}

__device__ __forceinline__ void gen_A12(
    const float* __restrict__ xsm, const float* __restrict__ hsm,
    uint32_t* __restrict__ Asm, int lch, int tid)
{
    const int m = tid >> 1;
    const int k0 = lch * 64 + (tid & 1) * 32;
    const int f = k0 >> 7, c0 = k0 & 127;
    const float xa = xsm[m * XS + f];
    const float2* hrow = (const float2*)(hsm + m * HS + c0);
    uint32_t* arow = Asm + m * AS + (tid & 1) * 16;
#pragma unroll
    for (int w = 0; w < 16; w++) {
        float2 hh = hrow[w];
        __half2 p = __floats2half2_rn(xa * hh.x, xa * hh.y);
        arow[w] = *(uint32_t*)&p;
    }
}

// ===================== per-chunk MMA (one k64 chunk) =======================
// warp grid 2M x 4N: wm in [0,2) -> 64-row tile (4 mt x 16);
//                    wn in [0,4) -> 64-col tile (8 n8-tiles)
// s-stage software pipeline: fragments for s+1 load during s's MMA bundle.
__device__ __forceinline__ void chunk_mma(
    uint32_t abase, uint32_t bbuf, int lane, int wm, int wn,
    float (&acc)[4][8][4])
{
    const int mtx = lane >> 3, rw = lane & 7;
    // ldmatrix x4 address: matrix0=(m0-7,kh0) m1=(m8-15,kh0) m2=(m0-7,kh1) m3=(m8-15,kh1)
    const uint32_t alane = abase
        + (uint32_t)((wm * 64 + rw + (mtx & 1) * 8) * 144)
        + (uint32_t)((mtx >> 1) * 16);
    const uint32_t blane = bbuf + (uint32_t)(wn * 2048 + lane * 16);

    uint32_t bfr[2][4][4], afr[2][4][4];
#pragma unroll
    for (int g = 0; g < 4; g++)
        lds128(bfr[0][g][0], bfr[0][g][1], bfr[0][g][2], bfr[0][g][3], blane + g * 512);
#pragma unroll
    for (int mt = 0; mt < 4; mt++)
        ldmx4(afr[0][mt], alane + mt * (16 * 144));

#pragma unroll
    for (int s = 0; s < 4; s++) {
        const int cur = s & 1, nxt = cur ^ 1;
        if (s < 3) {
#pragma unroll
            for (int g = 0; g < 4; g++)
                lds128(bfr[nxt][g][0], bfr[nxt][g][1], bfr[nxt][g][2], bfr[nxt][g][3],
                       blane + (s + 1) * 8192 + g * 512);
#pragma unroll
            for (int mt = 0; mt < 4; mt++)
                ldmx4(afr[nxt][mt], alane + (s + 1) * 32 + mt * (16 * 144));
        }
        // 32 independent MMAs hide the loads above
#pragma unroll
        for (int g = 0; g < 4; g++)
#pragma unroll
            for (int e = 0; e < 2; e++)
#pragma unroll
                for (int mt = 0; mt < 4; mt++)
                    mma_f16(acc[mt][g * 2 + e], afr[cur][mt],
                            bfr[cur][g][e * 2], bfr[cur][g][e * 2 + 1]);
    }
}

// ============================ main fused kernel ============================
__global__ void __launch_bounds__(NT, 1)
cin_mma(const float* __restrict__ x,
        const float* __restrict__ b0, const float* __restrict__ b1,
        const float* __restrict__ b2,
        const float* __restrict__ fcw, const float* __restrict__ fcb,
        float* __restrict__ out)
{
    extern __shared__ char sm[];
    const uint32_t smb = s2u(sm);
    float* xsm = (float*)(sm + SM_X);
    float* hsm = (float*)(sm + SM_H);
    float* rowsum = (float*)(sm + SM_RS);

    const int tid = threadIdx.x, wid = tid >> 5, lane = tid & 31;
    const int wm = wid & 1, wn = wid >> 1;
    const int m0 = blockIdx.x * MT;

    if (tid < MT) rowsum[tid] = 0.f;
    if (tid == 0) {
        MB_INIT(smb + SM_MB, 1); MB_INIT(smb + SM_MB + 8, 1); MB_INIT(smb + SM_MB + 16, 1);
    }

    // stage x tile: xsm[ml][f] = x[b, f, d];  m = m0+ml, b = m/32, d = m%32
    for (int i = tid; i < F_DIM * MT; i += NT) {
        int f = i >> 7, ml = i & 127, m = m0 + ml;
        xsm[ml * XS + f] = x[((size_t)(m >> 5) * F_DIM + f) * 32 + (m & 31)];
    }
    __syncthreads();    // x ready, mbarriers visible

    auto stage = [&](int gch) {
        if (tid == 0)
            bulk_ld(smb + SM_B + (gch % 3) * B_BUF, g_B + (size_t)gch * 2048, B_BUF,
                    smb + SM_MB + (gch % 3) * 8);
    };

    float acc[4][8][4];
    uint32_t ph[3] = {0, 0, 0};
    int gch = 0;
    stage(0);
    stage(1);

    for (int L = 0; L < 3; L++) {
        const int nch = (L == 0) ? NCH0 : NCH12;
#pragma unroll
        for (int mt = 0; mt < 4; mt++)
#pragma unroll
            for (int j = 0; j < 8; j++)
#pragma unroll
                for (int r = 0; r < 4; r++) acc[mt][j][r] = 0.f;

        for (int lch = 0; lch < nch; lch++, gch++) {
            const int q = gch % 3;
            uint32_t* Asm = (uint32_t*)(sm + SM_A + (gch & 1) * A_BUF);

            // A-gen for THIS chunk (A-buffer parity keeps it clear of the
            // previous chunk's still-running MMAs)
            if (L == 0) gen_A0(xsm, Asm, lch, tid);
            else        gen_A12(xsm, hsm, Asm, lch, tid);

            MB_WAIT(smb + SM_MB + q * 8, ph[q]);    // B chunk resident
            ph[q] ^= 1;
            __syncthreads();    // A visible; ALL warps done with chunk gch-1
                                // => buffer (gch+2)%3 (last used by gch-1) is free
            if (gch + 2 < NCHT) stage(gch + 2);

            chunk_mma(smb + SM_A + (gch & 1) * A_BUF,
                      smb + SM_B + q * B_BUF, lane, wm, wn, acc);
            // no trailing barrier: next chunk's sync re-converges
        }

        // ---- layer epilogue: bias+relu, h feedback, fc_w partial dots ----
        const float* bias = (L == 0) ? b0 : (L == 1) ? b1 : b2;
        const float* fa   = (L == 0) ? (fcw - 128) : (L == 1) ? fcw : (fcw + 256);
        const int cs      = (L < 2) ? 128 : 0;
        const bool wh     = (L < 2);
        float rs[8] = {0.f, 0.f, 0.f, 0.f, 0.f, 0.f, 0.f, 0.f};
#pragma unroll
        for (int mt = 0; mt < 4; mt++)
#pragma unroll
            for (int j = 0; j < 8; j++)
#pragma unroll
                for (int r = 0; r < 4; r++) {
                    int row = wm * 64 + mt * 16 + (lane >> 2) + ((r >> 1) << 3);
                    int col = wn * 64 + j * 8 + ((lane & 3) << 1) + (r & 1);
                    float v = fmaxf(acc[mt][j][r] + __ldg(&bias[col]), 0.f);
                    if (wh && col < 128) hsm[row * HS + col] = v;
                    if (col >= cs) rs[mt * 2 + (r >> 1)] += v * __ldg(&fa[col]);
                }
#pragma unroll
        for (int i = 0; i < 8; i++) {
            float v = rs[i];
            v += __shfl_xor_sync(0xffffffffu, v, 1);
            v += __shfl_xor_sync(0xffffffffu, v, 2);
            if ((lane & 3) == 0) {
                int row = wm * 64 + (i >> 1) * 16 + (lane >> 2) + ((i & 1) << 3);
                atomicAdd(&rowsum[row], v);
            }
        }
        __syncthreads();    // h + rowsum complete before next layer reads
    }

    // final: each 32-row group (= one batch element) reduces to one scalar
    if (tid < MT) {
        float v = rowsum[tid];
#pragma unroll
        for (int o = 16; o; o >>= 1) v += __shfl_xor_sync(0xffffffffu, v, o);
        if ((tid & 31) == 0) out[blockIdx.x * 4 + wid] = v + fcb[0];
    }
}

// ============================ launch =======================================
extern "C" void kernel_launch(void* const* d_in, const int* in_sizes, int n_in,
                              void* d_out, int out_size)
{
    const float* x   = (const float*)d_in[0];
    const float* W0  = (const float*)d_in[1];
    const float* b0  = (const float*)d_in[2];
    const float* W1  = (const float*)d_in[3];
    const float* b1  = (const float*)d_in[4];
    const float* W2  = (const float*)d_in[5];
    const float* b2  = (const float*)d_in[6];
    const float* fcw = (const float*)d_in[7];
    const float* fcb = (const float*)d_in[8];
    float* out = (float*)d_out;

    // weight shuffle/convert (every launch; idempotent, graph-capturable)
    const int conv_smem = 64 * 257 * 4;
    cudaFuncSetAttribute(conv_kernel, cudaFuncAttributeMaxDynamicSharedMemorySize, conv_smem);
    conv_kernel<<<NCH0,  256, conv_smem>>>(W0, K0_REAL, 0);
    conv_kernel<<<NCH12, 256, conv_smem>>>(W1, K12, NCH0);
    conv_kernel<<<NCH12, 256, conv_smem>>>(W2, K12, NCH0 + NCH12);

    int B = in_sizes[0] / (F_DIM * 32);      // 1024
    int grid = (B * 32) / MT;                // 256

    cudaFuncSetAttribute(cin_mma, cudaFuncAttributeMaxDynamicSharedMemorySize, SM_TOT);
    cin_mma<<<grid, NT, SM_TOT>>>(x, b0, b1, b2, fcw, fcb, out);
}

// round 14
// speedup vs baseline: 3.1403x; 1.1755x over previous
#include <cuda_runtime.h>
#include <cuda_fp16.h>
#include <stdint.h>

// ============================ problem constants ============================
#define F_DIM   39
#define NT      256
#define MT      64               // rows (b,d) per CTA = 2 batch elems
#define NCH0    24
#define NCH12   78
#define NCHT    (NCH0 + 2*NCH12) // 180
#define K0_REAL 1521
#define K12     4992

// weights: fp16, fragment order (verified R10-R13):
// 16B unit idx = ((s*16 + gp)*32 + lane)
__device__ __align__(256) uint4 g_B[(size_t)NCHT * 2048];

// ============================ smem layout (bytes) ==========================
#define B_BUF  32768                     // 2 buffers
#define SM_B   0
#define AS     36                        // A row stride in 4B words (144B)
#define A_BUF  (MT*AS*4)                 // 9216, 2 buffers
#define SM_A   (2*B_BUF)                 // 65536
#define SM_X   (SM_A + 2*A_BUF)          // 83968 : x fp32 [64][XS]
#define XS     41
#define HS2    136                       // h fp16 row stride (halfs); 272B = 16*17
#define SM_H   (SM_X + MT*XS*4)          // 94464 : h fp16 [64][HS2]
#define SM_RS  (SM_H + MT*HS2*2)         // 111872: rowsum[64]
#define SM_MB  (SM_RS + 256)             // 112128: 2 mbarriers
#define SM_TOT (SM_MB + 64)              // 112192  (x2 CTAs = 224384 < 228KB)

// ============================ helpers ======================================
__device__ __forceinline__ uint32_t s2u(const void* p) {
    uint32_t a;
    asm("{ .reg .u64 t; cvta.to.shared.u64 t, %1; cvt.u32.u64 %0, t; }" : "=r"(a) : "l"(p));
    return a;
}
#define MB_INIT(mb, c) asm volatile("mbarrier.init.shared.b64 [%0], %1;" :: "r"(mb), "r"(c) : "memory")

#define MB_WAIT(mb, par) do {                                                   \
    uint32_t _m = (mb), _p = (par), _d;                                         \
    asm volatile("{ .reg .pred p; mbarrier.try_wait.parity.shared.b64 p, [%1], %2; selp.b32 %0,1,0,p; }" \
        : "=r"(_d) : "r"(_m), "r"(_p) : "memory");                              \
    if (!_d) {                                                                  \
        asm volatile("{ .reg .pred P1; WL%=: mbarrier.try_wait.parity.shared.b64 P1, [%0], %1; @P1 bra.uni WD%=; bra.uni WL%=; WD%=: }" \
            :: "r"(_m), "r"(_p) : "memory");                                    \
    }                                                                           \
} while (0)

__device__ __forceinline__ void bulk_ld(uint32_t dst, const void* src, uint32_t bytes, uint32_t mb) {
    asm volatile("mbarrier.arrive.expect_tx.shared.b64 _, [%0], %1;" :: "r"(mb), "r"(bytes) : "memory");
    asm volatile("cp.async.bulk.shared::cluster.global.mbarrier::complete_tx::bytes [%0], [%1], %2, [%3];"
        :: "r"(dst), "l"(src), "r"(bytes), "r"(mb) : "memory");
}

__device__ __forceinline__ void mma_f16(float* c, const uint32_t* a, uint32_t b0, uint32_t b1) {
    asm volatile("mma.sync.aligned.m16n8k16.row.col.f32.f16.f16.f32 "
        "{%0,%1,%2,%3}, {%4,%5,%6,%7}, {%8,%9}, {%0,%1,%2,%3};"
        : "+f"(c[0]), "+f"(c[1]), "+f"(c[2]), "+f"(c[3])
        : "r"(a[0]), "r"(a[1]), "r"(a[2]), "r"(a[3]), "r"(b0), "r"(b1));
}
__device__ __forceinline__ void lds128(uint32_t& r0, uint32_t& r1, uint32_t& r2, uint32_t& r3, uint32_t a) {
    asm volatile("ld.shared.v4.u32 {%0,%1,%2,%3}, [%4];"
        : "=r"(r0), "=r"(r1), "=r"(r2), "=r"(r3) : "r"(a));
}
__device__ __forceinline__ void ldmx4(uint32_t* r, uint32_t a) {
    asm volatile("ldmatrix.sync.aligned.m8n8.x4.shared.b16 {%0,%1,%2,%3}, [%4];"
        : "=r"(r[0]), "=r"(r[1]), "=r"(r[2]), "=r"(r[3]) : "r"(a));
}

// ================= weight shuffle kernel (fragment order) ==================
__global__ void conv_kernel(const float* __restrict__ W, int Kreal, int chunk0) {
    extern __shared__ float ws[];     // [64][257]
    const int lc = blockIdx.x, tid = threadIdx.x;
    for (int i = 0; i < 64; i++) {
        int k = lc * 64 + i;
        ws[i * 257 + tid] = (k < Kreal) ? W[(size_t)k * 256 + tid] : 0.f;
    }
    __syncthreads();
    const size_t base = (size_t)(chunk0 + lc) * 2048;
    for (int u = tid; u < 2048; u += 256) {
        int lane = u & 31, gp = (u >> 5) & 15, s = (u >> 9) & 3;
        int kb = s * 16 + (lane & 3) * 2;
        uint32_t wreg[4];
#pragma unroll
        for (int e = 0; e < 2; e++) {
            int n = (gp * 2 + e) * 8 + (lane >> 2);
            __half2 w0 = __floats2half2_rn(ws[kb * 257 + n],       ws[(kb + 1) * 257 + n]);
            __half2 w1 = __floats2half2_rn(ws[(kb + 8) * 257 + n], ws[(kb + 9) * 257 + n]);
            wreg[e * 2]     = *(uint32_t*)&w0;
            wreg[e * 2 + 1] = *(uint32_t*)&w1;
        }
        g_B[base + u] = make_uint4(wreg[0], wreg[1], wreg[2], wreg[3]);
    }
}

// =============== cooperative A generation: fp16 into SMEM ==================
// thread tid -> row m = tid/4, k-quarter kq = tid&3 (16 k each = 8 half2)

// layer 0 (HP=39): scalar f/c walk over fp32 x
__device__ __forceinline__ void gen_A0(
    const float* __restrict__ xsm, uint32_t* __restrict__ Asm,
    int lch, int tid)
{
    const int m = tid >> 2;
    const int k0 = lch * 64 + (tid & 3) * 16;
    int f = k0 / F_DIM, c = k0 - f * F_DIM;
    const float* xrow = xsm + m * XS;
    uint32_t w8[8];
    float xa = xrow[f];
#pragma unroll
    for (int w = 0; w < 8; w++) {
        const int k = k0 + w * 2;
        float a0 = (k < K0_REAL) ? xa * xrow[c] : 0.f;
        if (++c == F_DIM) { c = 0; xa = xrow[++f]; }
        float a1 = (k + 1 < K0_REAL) ? xa * xrow[c] : 0.f;
        if (++c == F_DIM) { c = 0; xa = xrow[++f]; }
        __half2 p = __floats2half2_rn(a0, a1);
        w8[w] = *(uint32_t*)&p;
    }
    uint4* dst = (uint4*)(Asm + m * AS + (tid & 3) * 8);
    dst[0] = make_uint4(w8[0], w8[1], w8[2], w8[3]);
    dst[1] = make_uint4(w8[4], w8[5], w8[6], w8[7]);
}

// layers 1/2 (HP=128): h is fp16 in smem; product in fp32, round to fp16
__device__ __forceinline__ void gen_A12(
    const float* __restrict__ xsm, const __half* __restrict__ hsm,
    uint32_t* __restrict__ Asm, int lch, int tid)
{
    const int m = tid >> 2;
    const int k0 = lch * 64 + (tid & 3) * 16;
    const int f = k0 >> 7, c0 = k0 & 127;
    const float xa = xsm[m * XS + f];
    const uint4* hrow = (const uint4*)(hsm + m * HS2 + c0);
    uint4* dst = (uint4*)(Asm + m * AS + (tid & 3) * 8);
#pragma unroll
    for (int half16 = 0; half16 < 2; half16++) {
        uint4 hv = hrow[half16];
        uint32_t hw[4] = { hv.x, hv.y, hv.z, hv.w };
        uint32_t ow[4];
#pragma unroll
        for (int e = 0; e < 4; e++) {
            float2 hf = __half22float2(*(__half2*)&hw[e]);
            __half2 p = __floats2half2_rn(xa * hf.x, xa * hf.y);
            ow[e] = *(uint32_t*)&p;
        }
        dst[half16] = make_uint4(ow[0], ow[1], ow[2], ow[3]);
    }
}

// ===================== per-chunk MMA (one k64 chunk) =======================
// warp grid 2M x 4N: wm in [0,2) -> 32-row tile (2 mt x 16);
//                    wn in [0,4) -> 64-col tile
__device__ __forceinline__ void chunk_mma(
    uint32_t abase, uint32_t bbuf, int lane, int wm, int wn,
    float (&acc)[2][8][4])
{
    const int mtx = lane >> 3, rw = lane & 7;
    // ldmatrix x4: mat0=(r0-7,kh0) mat1=(r8-15,kh0) mat2=(r0-7,kh1) mat3=(r8-15,kh1)
    const uint32_t alane = abase
        + (uint32_t)((wm * 32 + rw + (mtx & 1) * 8) * 144)
        + (uint32_t)((mtx >> 1) * 16);
    const uint32_t blane = bbuf + (uint32_t)(wn * 2048 + lane * 16);

#pragma unroll
    for (int s = 0; s < 4; s++) {
        uint32_t bfr[4][4], afr[2][4];
#pragma unroll
        for (int g = 0; g < 4; g++)
            lds128(bfr[g][0], bfr[g][1], bfr[g][2], bfr[g][3],
                   blane + s * 8192 + g * 512);
#pragma unroll
        for (int mt = 0; mt < 2; mt++)
            ldmx4(afr[mt], alane + s * 32 + mt * (16 * 144));
#pragma unroll
        for (int g = 0; g < 4; g++)
#pragma unroll
            for (int e = 0; e < 2; e++)
#pragma unroll
                for (int mt = 0; mt < 2; mt++)
                    mma_f16(acc[mt][g * 2 + e], afr[mt],
                            bfr[g][e * 2], bfr[g][e * 2 + 1]);
    }
}

// ============================ main fused kernel ============================
__global__ void __launch_bounds__(NT, 2)
cin_mma(const float* __restrict__ x,
        const float* __restrict__ b0, const float* __restrict__ b1,
        const float* __restrict__ b2,
        const float* __restrict__ fcw, const float* __restrict__ fcb,
        float* __restrict__ out)
{
    extern __shared__ char sm[];
    const uint32_t smb = s2u(sm);
    float* xsm = (float*)(sm + SM_X);
    __half* hsm = (__half*)(sm + SM_H);
    float* rowsum = (float*)(sm + SM_RS);

    const int tid = threadIdx.x, wid = tid >> 5, lane = tid & 31;
    const int wm = wid & 1, wn = wid >> 1;
    const int m0 = blockIdx.x * MT;

    if (tid < MT) rowsum[tid] = 0.f;
    if (tid == 0) { MB_INIT(smb + SM_MB, 1); MB_INIT(smb + SM_MB + 8, 1); }

    // stage x tile: xsm[ml][f] = x[b, f, d];  m = m0+ml
    for (int i = tid; i < F_DIM * MT; i += NT) {
        int f = i >> 6, ml = i & 63, m = m0 + ml;
        xsm[ml * XS + f] = x[((size_t)(m >> 5) * F_DIM + f) * 32 + (m & 31)];
    }
    __syncthreads();    // x ready, mbarriers visible

    auto stage = [&](int gch) {
        if (tid == 0)
            bulk_ld(smb + SM_B + (gch & 1) * B_BUF, g_B + (size_t)gch * 2048, B_BUF,
                    smb + SM_MB + (gch & 1) * 8);
    };

    float acc[2][8][4];
    uint32_t ph[2] = {0, 0};
    int gch = 0;
    stage(0);

    for (int L = 0; L < 3; L++) {
        const int nch = (L == 0) ? NCH0 : NCH12;
#pragma unroll
        for (int mt = 0; mt < 2; mt++)
#pragma unroll
            for (int j = 0; j < 8; j++)
#pragma unroll
                for (int r = 0; r < 4; r++) acc[mt][j][r] = 0.f;

        for (int lch = 0; lch < nch; lch++, gch++) {
            const int q = gch & 1;
            uint32_t* Asm = (uint32_t*)(sm + SM_A + q * A_BUF);

            if (L == 0) gen_A0(xsm, Asm, lch, tid);
            else        gen_A12(xsm, hsm, Asm, lch, tid);

            MB_WAIT(smb + SM_MB + q * 8, ph[q]);
            ph[q] ^= 1;
            __syncthreads();    // A visible; all warps done chunk gch-1
                                // => buffer (gch+1)&1 (used by gch-1) is free
            if (gch + 1 < NCHT) stage(gch + 1);

            chunk_mma(smb + SM_A + q * A_BUF, smb + SM_B + q * B_BUF,
                      lane, wm, wn, acc);
            // no trailing barrier; next chunk's sync re-converges
        }

        // ---- layer epilogue: bias+relu, h feedback (fp16), fc_w dots ----
        const float* bias = (L == 0) ? b0 : (L == 1) ? b1 : b2;
        const float* fa   = (L == 0) ? (fcw - 128) : (L == 1) ? fcw : (fcw + 256);
        const int cs      = (L < 2) ? 128 : 0;
        const bool wh     = (L < 2);
        float rs[4] = {0.f, 0.f, 0.f, 0.f};
#pragma unroll
        for (int mt = 0; mt < 2; mt++)
#pragma unroll
            for (int j = 0; j < 8; j++)
#pragma unroll
                for (int r = 0; r < 4; r++) {
                    int row = wm * 32 + mt * 16 + (lane >> 2) + ((r >> 1) << 3);
                    int col = wn * 64 + j * 8 + ((lane & 3) << 1) + (r & 1);
                    float v = fmaxf(acc[mt][j][r] + __ldg(&bias[col]), 0.f);
                    if (wh && col < 128) hsm[row * HS2 + col] = __float2half(v);
                    if (col >= cs) rs[mt * 2 + (r >> 1)] += v * __ldg(&fa[col]);
                }
#pragma unroll
        for (int i = 0; i < 4; i++) {
            float v = rs[i];
            v += __shfl_xor_sync(0xffffffffu, v, 1);
            v += __shfl_xor_sync(0xffffffffu, v, 2);
            if ((lane & 3) == 0) {
                int row = wm * 32 + (i >> 1) * 16 + (lane >> 2) + ((i & 1) << 3);
                atomicAdd(&rowsum[row], v);
            }
        }
        __syncthreads();    // h + rowsum complete before next layer's gen
    }

    // final: each 32-row group (= one batch element) reduces to one scalar
    if (tid < MT) {
        float v = rowsum[tid];
#pragma unroll
        for (int o = 16; o; o >>= 1) v += __shfl_xor_sync(0xffffffffu, v, o);
        if ((tid & 31) == 0) out[blockIdx.x * 2 + wid] = v + fcb[0];
    }
}

// ============================ launch =======================================
extern "C" void kernel_launch(void* const* d_in, const int* in_sizes, int n_in,
                              void* d_out, int out_size)
{
    const float* x   = (const float*)d_in[0];
    const float* W0  = (const float*)d_in[1];
    const float* b0  = (const float*)d_in[2];
    const float* W1  = (const float*)d_in[3];
    const float* b1  = (const float*)d_in[4];
    const float* W2  = (const float*)d_in[5];
    const float* b2  = (const float*)d_in[6];
    const float* fcw = (const float*)d_in[7];
    const float* fcb = (const float*)d_in[8];
    float* out = (float*)d_out;

    // weight shuffle/convert (every launch; idempotent, graph-capturable)
    const int conv_smem = 64 * 257 * 4;
    cudaFuncSetAttribute(conv_kernel, cudaFuncAttributeMaxDynamicSharedMemorySize, conv_smem);
    conv_kernel<<<NCH0,  256, conv_smem>>>(W0, K0_REAL, 0);
    conv_kernel<<<NCH12, 256, conv_smem>>>(W1, K12, NCH0);
    conv_kernel<<<NCH12, 256, conv_smem>>>(W2, K12, NCH0 + NCH12);

    int B = in_sizes[0] / (F_DIM * 32);      // 1024
    int grid = (B * 32) / MT;                // 512

    cudaFuncSetAttribute(cin_mma, cudaFuncAttributeMaxDynamicSharedMemorySize, SM_TOT);
    cin_mma<<<grid, NT, SM_TOT>>>(x, b0, b1, b2, fcw, fcb, out);
}